// round 4
// baseline (speedup 1.0000x reference)
#include <cuda_runtime.h>
#include <cuda_bf16.h>
#include <cstdint>

#define BATCH 16
#define CIN   256
#define HH    80
#define WW    80
#define CMID  64
#define K2T   25
#define HO    160
#define WO    160
#define EPS   1e-5f

// ---------------------------------------------------------------------------
// Device scratch (allocation-free)
// ---------------------------------------------------------------------------
__device__ __align__(16) __nv_bfloat16 g_midT_hi[(size_t)BATCH * 6400 * 64]; // [b][pix][c]
__device__ __align__(16) __nv_bfloat16 g_midT_lo[(size_t)BATCH * 6400 * 64];
// per-tap weights, n-major: [tap][split][c(112)][ic(72)] bf16
__device__ __align__(16) __nv_bfloat16 g_weP[9 * 2 * 112 * 72];
__device__ __align__(16) float g_wm[(size_t)BATCH * K2T * HO * WO];

__device__ __forceinline__ uint32_t smem_u32(const void* p) {
    uint32_t a;
    asm("{ .reg .u64 t; cvta.to.shared.u64 t, %1; cvt.u32.u64 %0, t; }" : "=r"(a) : "l"(p));
    return a;
}
__device__ __forceinline__ void ldsm_x4(uint32_t& r0, uint32_t& r1, uint32_t& r2, uint32_t& r3,
                                        uint32_t addr) {
    asm volatile("ldmatrix.sync.aligned.m8n8.x4.shared.b16 {%0,%1,%2,%3}, [%4];"
                 : "=r"(r0), "=r"(r1), "=r"(r2), "=r"(r3) : "r"(addr));
}
__device__ __forceinline__ void ldsm_x2(uint32_t& r0, uint32_t& r1, uint32_t addr) {
    asm volatile("ldmatrix.sync.aligned.m8n8.x2.shared.b16 {%0,%1}, [%2];"
                 : "=r"(r0), "=r"(r1) : "r"(addr));
}
__device__ __forceinline__ void mma16816(float* d, const uint32_t* a, uint32_t b0, uint32_t b1) {
    asm volatile(
        "mma.sync.aligned.m16n8k16.row.col.f32.bf16.bf16.f32 "
        "{%0,%1,%2,%3}, {%4,%5,%6,%7}, {%8,%9}, {%0,%1,%2,%3};"
        : "+f"(d[0]), "+f"(d[1]), "+f"(d[2]), "+f"(d[3])
        : "r"(a[0]), "r"(a[1]), "r"(a[2]), "r"(a[3]), "r"(b0), "r"(b1));
}
// Packed fp32 helpers (Blackwell f32x2 pipe)
__device__ __forceinline__ void fma2(uint64_t& d, uint64_t a, uint64_t b) {
    asm("fma.rn.f32x2 %0, %1, %2, %0;" : "+l"(d) : "l"(a), "l"(b));
}
__device__ __forceinline__ uint64_t bcast2(float x) {
    uint64_t r;
    asm("mov.b64 %0, {%1, %1};" : "=l"(r) : "f"(x));
    return r;
}
__device__ __forceinline__ void unpack2(float& lo, float& hi, uint64_t v) {
    asm("mov.b64 {%0, %1}, %2;" : "=f"(lo), "=f"(hi) : "l"(v));
}
__device__ __forceinline__ void lds_v2u64(uint64_t& a, uint64_t& b, uint32_t addr) {
    asm volatile("ld.shared.v2.u64 {%0, %1}, [%2];" : "=l"(a), "=l"(b) : "r"(addr));
}

// ---------------------------------------------------------------------------
// K0: weights -> [tap][split][c pad 112][ic pad 72] bf16 split
// ---------------------------------------------------------------------------
__global__ __launch_bounds__(256) void k0_wprep(const float* __restrict__ We) {
    int i = blockIdx.x * 256 + threadIdx.x;
    if (i >= 9 * 2 * 112 * 72) return;
    int tap = i / 16128, r = i % 16128;
    int s = r / 8064; r %= 8064;
    int c = r / 72, ic = r % 72;
    float v = (c < 100 && ic < 64) ? We[c * 576 + ic * 9 + tap] : 0.f;
    __nv_bfloat16 hi = __float2bfloat16(v);
    g_weP[i] = s ? __float2bfloat16(v - __bfloat162float(hi)) : hi;
}

// ---------------------------------------------------------------------------
// K1: 1x1 conv (256->64) + BN + SiLU -> bf16 split, pixel-major [b][pix][c]
// ---------------------------------------------------------------------------
__global__ __launch_bounds__(256) void k1_comp(
    const float* __restrict__ X, const float* __restrict__ Wc,
    const float* __restrict__ g1, const float* __restrict__ b1,
    const float* __restrict__ m1, const float* __restrict__ v1)
{
    const int b  = blockIdx.y;
    const int p0 = blockIdx.x * 64;

    __shared__ __align__(16) float Xs[32][68];
    __shared__ __align__(16) float Ws[32][68];
    __shared__ __align__(16) __nv_bfloat16 s_hi[64][72];
    __shared__ __align__(16) __nv_bfloat16 s_lo[64][72];

    const int tx = threadIdx.x & 15;
    const int ty = threadIdx.x >> 4;

    float acc[4][4];
#pragma unroll
    for (int i = 0; i < 4; i++)
#pragma unroll
        for (int j = 0; j < 4; j++) acc[i][j] = 0.f;

    const float* Xb = X + (size_t)b * CIN * (HH * WW) + p0;

    for (int k0 = 0; k0 < CIN; k0 += 32) {
        for (int i = threadIdx.x; i < 2048; i += 256) {
            int kk = i >> 6, nn = i & 63;
            Xs[kk][nn] = Xb[(size_t)(k0 + kk) * (HH * WW) + nn];
        }
        for (int i = threadIdx.x; i < 2048; i += 256) {
            int m = i >> 5, kk = i & 31;
            Ws[kk][m] = Wc[m * CIN + k0 + kk];
        }
        __syncthreads();
#pragma unroll
        for (int kk = 0; kk < 32; kk++) {
            float4 a  = *(const float4*)&Ws[kk][ty * 4];
            float4 bb = *(const float4*)&Xs[kk][tx * 4];
            float av[4] = {a.x, a.y, a.z, a.w};
            float bv[4] = {bb.x, bb.y, bb.z, bb.w};
#pragma unroll
            for (int i = 0; i < 4; i++)
#pragma unroll
                for (int j = 0; j < 4; j++) acc[i][j] += av[i] * bv[j];
        }
        __syncthreads();
    }

#pragma unroll
    for (int i = 0; i < 4; i++) {
        int m = ty * 4 + i;
        float is = g1[m] * rsqrtf(v1[m] + EPS);
        float bi = b1[m] - m1[m] * is;
#pragma unroll
        for (int j = 0; j < 4; j++) {
            float v = acc[i][j] * is + bi;
            float sv = v / (1.f + __expf(-v));
            __nv_bfloat16 hi = __float2bfloat16(sv);
            s_hi[tx * 4 + j][m] = hi;
            s_lo[tx * 4 + j][m] = __float2bfloat16(sv - __bfloat162float(hi));
        }
    }
    __syncthreads();

    for (int i = threadIdx.x; i < 1024; i += 256) {
        int bufi = i >> 9, r = (i >> 3) & 63, ch = i & 7;
        uint4 v = bufi ? *(const uint4*)&s_lo[r][ch * 8] : *(const uint4*)&s_hi[r][ch * 8];
        uint4* dst = (uint4*)(bufi ? g_midT_lo : g_midT_hi);
        dst[(size_t)(b * 6400 + p0 + r) * 8 + ch] = v;
    }
}

// ---------------------------------------------------------------------------
// K2: 3x3 conv (64->100) via mma.sync bf16 split-3 + BN + shuffle + softmax
// ---------------------------------------------------------------------------
#define SM_ACT_HI 0
#define SM_ACT_LO 25920
#define SM_W      51840
#define SM_SCS    84096
#define SM_BIS    84496
#define SM_TOTAL  84992
#define DT_STRIDE 122

__global__ __launch_bounds__(256, 2)
void k2_enc(const float* __restrict__ g2, const float* __restrict__ b2,
            const float* __restrict__ m2, const float* __restrict__ v2)
{
    extern __shared__ __align__(16) char sm[];
    const int b  = blockIdx.z;
    const int h0 = blockIdx.y * 16;
    const int w0 = blockIdx.x * 8;
    const int tid = threadIdx.x;
    const int wid = tid >> 5;
    const int lan = tid & 31;
    const uint32_t smb = smem_u32(sm);

    if (tid < 100) {
        float is = g2[tid] * rsqrtf(v2[tid] + EPS);
        ((float*)(sm + SM_SCS))[tid] = is;
        ((float*)(sm + SM_BIS))[tid] = b2[tid] - m2[tid] * is;
    }

    for (int k = tid; k < 2880; k += 256) {
        int bufi = (k >= 1440);
        int r = bufi ? k - 1440 : k;
        int row = r >> 3, ch = r & 7;
        int y = row / 10, x = row - y * 10;
        int gh = h0 + y - 1, gw = w0 + x - 1;
        uint4 v = make_uint4(0, 0, 0, 0);
        if (gh >= 0 && gh < HH && gw >= 0 && gw < WW) {
            const uint4* src = (const uint4*)(bufi ? g_midT_lo : g_midT_hi);
            v = src[(size_t)(b * 6400 + gh * WW + gw) * 8 + ch];
        }
        *(uint4*)(sm + (bufi ? SM_ACT_LO : SM_ACT_HI) + row * 144 + (ch << 4)) = v;
    }

    const int warpm = wid & 3;
    const int warpn = wid >> 2;

    float acc[2][7][4];
#pragma unroll
    for (int mb = 0; mb < 2; mb++)
#pragma unroll
        for (int nb = 0; nb < 7; nb++)
#pragma unroll
            for (int j = 0; j < 4; j++) acc[mb][nb][j] = 0.f;

    const int pA0 = warpm * 32 + (lan & 15);
    const int pyA0 = pA0 >> 3, pxA0 = pA0 & 7;
    const uint32_t a_half = (uint32_t)((lan >> 4) << 4);
    const int cB = warpn * 56 + (lan & 7);
    const uint32_t b_half = (uint32_t)(((lan >> 3) & 1) << 4);
    const uint32_t wb_hi = smb + SM_W + (uint32_t)cB * 144 + b_half;
    const uint32_t wb_lo = wb_hi + 16128;

    for (int tap = 0; tap < 9; tap++) {
        const int dy = tap / 3, dx = tap - dy * 3;
        __syncthreads();
        {
            const uint4* gsrc = (const uint4*)g_weP + tap * 2016;
            for (int k = tid; k < 2016; k += 256)
                *(uint4*)(sm + SM_W + (k << 4)) = gsrc[k];
        }
        __syncthreads();

        uint32_t arow0 = (uint32_t)(((pyA0 + dy) * 10 + pxA0 + dx) * 144) + a_half;
        uint32_t arow1 = (uint32_t)(((((pA0 + 16) >> 3) + dy) * 10 + ((pA0 + 16) & 7) + dx) * 144) + a_half;

#pragma unroll
        for (int ks = 0; ks < 4; ks++) {
            const uint32_t ko = (uint32_t)(ks << 5);
            uint32_t Ah[2][4], Al[2][4];
            ldsm_x4(Ah[0][0], Ah[0][1], Ah[0][2], Ah[0][3], smb + SM_ACT_HI + arow0 + ko);
            ldsm_x4(Ah[1][0], Ah[1][1], Ah[1][2], Ah[1][3], smb + SM_ACT_HI + arow1 + ko);
            ldsm_x4(Al[0][0], Al[0][1], Al[0][2], Al[0][3], smb + SM_ACT_LO + arow0 + ko);
            ldsm_x4(Al[1][0], Al[1][1], Al[1][2], Al[1][3], smb + SM_ACT_LO + arow1 + ko);
#pragma unroll
            for (int nb = 0; nb < 7; nb++) {
                uint32_t bh0, bh1, bl0, bl1;
                ldsm_x2(bh0, bh1, wb_hi + (uint32_t)(nb * 1152) + ko);
                ldsm_x2(bl0, bl1, wb_lo + (uint32_t)(nb * 1152) + ko);
#pragma unroll
                for (int mb = 0; mb < 2; mb++) {
                    mma16816(acc[mb][nb], Ah[mb], bh0, bh1);
                    mma16816(acc[mb][nb], Ah[mb], bl0, bl1);
                    mma16816(acc[mb][nb], Al[mb], bh0, bh1);
                }
            }
        }
    }
    __syncthreads();

    float* Dt = (float*)sm;
#pragma unroll
    for (int mb = 0; mb < 2; mb++) {
        int r = warpm * 32 + mb * 16 + (lan >> 2);
#pragma unroll
        for (int nb = 0; nb < 7; nb++) {
            int c = warpn * 56 + nb * 8 + 2 * (lan & 3);
            *(float2*)&Dt[r * DT_STRIDE + c] = make_float2(acc[mb][nb][0], acc[mb][nb][1]);
            *(float2*)&Dt[(r + 8) * DT_STRIDE + c] = make_float2(acc[mb][nb][2], acc[mb][nb][3]);
        }
    }
    __syncthreads();

    const float* scs = (const float*)(sm + SM_SCS);
    const float* bis = (const float*)(sm + SM_BIS);
    for (int it = tid; it < 512; it += 256) {
        int p = it >> 2, q = it & 3;
        float v[25];
        float mx = -1e30f;
#pragma unroll
        for (int k = 0; k < 25; k++) {
            int m = (k << 2) + q;
            float x = Dt[p * DT_STRIDE + m] * scs[m] + bis[m];
            v[k] = x;
            mx = fmaxf(mx, x);
        }
        float s = 0.f;
#pragma unroll
        for (int k = 0; k < 25; k++) {
            float e = __expf(v[k] - mx);
            v[k] = e;
            s += e;
        }
        float inv = 1.f / s;
        int y = 2 * (h0 + (p >> 3)) + (q >> 1);
        int x = 2 * (w0 + (p & 7)) + (q & 1);
#pragma unroll
        for (int k = 0; k < 25; k++)
            g_wm[(((size_t)(b * K2T + k)) * HO + y) * WO + x] = v[k] * inv;
    }
}

// ---------------------------------------------------------------------------
// K3 v2: CARAFE reassembly — channel-fastest smem, immediate-offset LDS,
//        packed f32x2 FMA. 8x8 low-res tile, 8 cgs of 32 channels.
// ---------------------------------------------------------------------------
#define XST 36   // Xs float stride per position (144B, 16B-aligned, conflict-free reads)

__global__ __launch_bounds__(256, 2) void k3_carafe(
    const float* __restrict__ X, float* __restrict__ out)
{
    const int b = blockIdx.y;
    const int h0 = (blockIdx.x / 10) * 8;
    const int w0 = (blockIdx.x % 10) * 8;

    __shared__ __align__(16) float Ws4[25][64][4];   // 25.6KB
    __shared__ __align__(16) float Xs[144 * XST];    // 20.7KB

    const int tid = threadIdx.x;

    // softmaxed weights for this tile (float2-coalesced from g_wm)
    for (int i = tid; i < 3200; i += 256) {
        int kk = i / 128, r = i % 128, si = r >> 6, p = r & 63;
        int h = p >> 3, w = p & 7;
        int y = 2 * (h0 + h) + si, x = 2 * (w0 + w);
        float2 v = *(const float2*)&g_wm[(((size_t)(b * K2T + kk)) * HO + y) * WO + x];
        Ws4[kk][p][si * 2 + 0] = v.x;
        Ws4[kk][p][si * 2 + 1] = v.y;
    }

    const int px = tid & 63, g = tid >> 6;
    const int h = px >> 3, w = px & 7;
    const uint32_t xbase = smem_u32(Xs) + (uint32_t)(((h * 12 + w) * XST + g * 8) * 4);
    const uint32_t wbase = smem_u32(Ws4) + (uint32_t)(px * 16);

    const int y0 = 2 * (h0 + h), x0 = 2 * (w0 + w);

    for (int cg = 0; cg < 8; cg++) {
        __syncthreads();   // Ws4 ready (first iter) / Xs reusable
        // stage 32 ch x 144 pos, channel-fastest
        for (int i = tid; i < 4608; i += 256) {
            int cc = i / 144, r = i - cc * 144;
            int dy = r / 12, dx = r - dy * 12;
            int gh = h0 + dy - 2, gw = w0 + dx - 2;
            float val = 0.f;
            if (gh >= 0 && gh < HH && gw >= 0 && gw < WW)
                val = X[(((size_t)(b * CIN + cg * 32 + cc)) * HH + gh) * WW + gw];
            Xs[r * XST + cc] = val;
        }
        __syncthreads();

        uint64_t acc[4][4];   // [subpix s][ch pair]
#pragma unroll
        for (int s = 0; s < 4; s++)
#pragma unroll
            for (int p = 0; p < 4; p++) acc[s][p] = 0ull;

#pragma unroll
        for (int t = 0; t < 25; t++) {
            const int ki = t / 5, kj = t - ki * 5;
            float4 wv = *(const float4*)((const char*)Ws4 + (wbase - smem_u32(Ws4)) + t * 1024);
            uint64_t w2[4] = { bcast2(wv.x), bcast2(wv.y), bcast2(wv.z), bcast2(wv.w) };
            uint64_t xp[4];
            lds_v2u64(xp[0], xp[1], xbase + (uint32_t)((ki * 12 + kj) * XST * 4));
            lds_v2u64(xp[2], xp[3], xbase + (uint32_t)(((ki * 12 + kj) * XST + 4) * 4));
#pragma unroll
            for (int s = 0; s < 4; s++) {
                fma2(acc[s][0], xp[0], w2[s]);
                fma2(acc[s][1], xp[1], w2[s]);
                fma2(acc[s][2], xp[2], w2[s]);
                fma2(acc[s][3], xp[3], w2[s]);
            }
        }

        // stores: per channel, float2 along x (sj pairs) -> coalesced
#pragma unroll
        for (int p = 0; p < 4; p++) {
            float v00a, v00b, v01a, v01b, v10a, v10b, v11a, v11b;
            unpack2(v00a, v00b, acc[0][p]);
            unpack2(v01a, v01b, acc[1][p]);
            unpack2(v10a, v10b, acc[2][p]);
            unpack2(v11a, v11b, acc[3][p]);
            int c0 = cg * 32 + g * 8 + 2 * p;
            float* o0 = &out[(((size_t)(b * CIN + c0)) * HO + y0) * WO + x0];
            float* o1 = &out[(((size_t)(b * CIN + c0 + 1)) * HO + y0) * WO + x0];
            *(float2*)o0          = make_float2(v00a, v01a);
            *(float2*)(o0 + WO)   = make_float2(v10a, v11a);
            *(float2*)o1          = make_float2(v00b, v01b);
            *(float2*)(o1 + WO)   = make_float2(v10b, v11b);
        }
    }
}

// ---------------------------------------------------------------------------
extern "C" void kernel_launch(void* const* d_in, const int* in_sizes, int n_in,
                              void* d_out, int out_size)
{
    const float* X  = (const float*)d_in[0];
    const float* Wc = (const float*)d_in[1];
    const float* g1 = (const float*)d_in[2];
    const float* b1 = (const float*)d_in[3];
    const float* m1 = (const float*)d_in[4];
    const float* v1 = (const float*)d_in[5];
    const float* We = (const float*)d_in[6];
    const float* g2 = (const float*)d_in[7];
    const float* b2 = (const float*)d_in[8];
    const float* m2 = (const float*)d_in[9];
    const float* v2 = (const float*)d_in[10];
    float* out = (float*)d_out;

    cudaFuncSetAttribute(k2_enc, cudaFuncAttributeMaxDynamicSharedMemorySize, SM_TOTAL);

    k0_wprep<<<568, 256>>>(We);
    k1_comp<<<dim3(100, BATCH), 256>>>(X, Wc, g1, b1, m1, v1);
    k2_enc<<<dim3(10, 5, BATCH), 256, SM_TOTAL>>>(g2, b2, m2, v2);
    k3_carafe<<<dim3(100, BATCH), 256>>>(X, out);
}

// round 5
// speedup vs baseline: 1.1432x; 1.1432x over previous
#include <cuda_runtime.h>
#include <cuda_bf16.h>
#include <cstdint>

#define BATCH 16
#define CIN   256
#define HH    80
#define WW    80
#define CMID  64
#define K2T   25
#define HO    160
#define WO    160
#define EPS   1e-5f

// ---------------------------------------------------------------------------
// Device scratch (allocation-free)
// ---------------------------------------------------------------------------
__device__ __align__(16) __nv_bfloat16 g_midT_hi[(size_t)BATCH * 6400 * 64]; // [b][pix][c]
__device__ __align__(16) __nv_bfloat16 g_midT_lo[(size_t)BATCH * 6400 * 64];
// per-tap weights, n-major: [tap][split][c(112)][ic(72)] bf16
__device__ __align__(16) __nv_bfloat16 g_weP[9 * 2 * 112 * 72];
__device__ __align__(16) float g_wm[(size_t)BATCH * K2T * HO * WO];

__device__ __forceinline__ uint32_t smem_u32(const void* p) {
    uint32_t a;
    asm("{ .reg .u64 t; cvta.to.shared.u64 t, %1; cvt.u32.u64 %0, t; }" : "=r"(a) : "l"(p));
    return a;
}
__device__ __forceinline__ void ldsm_x4(uint32_t& r0, uint32_t& r1, uint32_t& r2, uint32_t& r3,
                                        uint32_t addr) {
    asm volatile("ldmatrix.sync.aligned.m8n8.x4.shared.b16 {%0,%1,%2,%3}, [%4];"
                 : "=r"(r0), "=r"(r1), "=r"(r2), "=r"(r3) : "r"(addr));
}
__device__ __forceinline__ void ldsm_x2(uint32_t& r0, uint32_t& r1, uint32_t addr) {
    asm volatile("ldmatrix.sync.aligned.m8n8.x2.shared.b16 {%0,%1}, [%2];"
                 : "=r"(r0), "=r"(r1) : "r"(addr));
}
__device__ __forceinline__ void mma16816(float* d, const uint32_t* a, uint32_t b0, uint32_t b1) {
    asm volatile(
        "mma.sync.aligned.m16n8k16.row.col.f32.bf16.bf16.f32 "
        "{%0,%1,%2,%3}, {%4,%5,%6,%7}, {%8,%9}, {%0,%1,%2,%3};"
        : "+f"(d[0]), "+f"(d[1]), "+f"(d[2]), "+f"(d[3])
        : "r"(a[0]), "r"(a[1]), "r"(a[2]), "r"(a[3]), "r"(b0), "r"(b1));
}
// Packed fp32 helpers (Blackwell f32x2 pipe)
__device__ __forceinline__ void fma2(uint64_t& d, uint64_t a, uint64_t b) {
    asm("fma.rn.f32x2 %0, %1, %2, %0;" : "+l"(d) : "l"(a), "l"(b));
}
__device__ __forceinline__ uint64_t bcast2(float x) {
    uint64_t r;
    asm("mov.b64 %0, {%1, %1};" : "=l"(r) : "f"(x));
    return r;
}
__device__ __forceinline__ void unpack2(float& lo, float& hi, uint64_t v) {
    asm("mov.b64 {%0, %1}, %2;" : "=f"(lo), "=f"(hi) : "l"(v));
}
__device__ __forceinline__ void lds_v2u64(uint64_t& a, uint64_t& b, uint32_t addr) {
    asm volatile("ld.shared.v2.u64 {%0, %1}, [%2];" : "=l"(a), "=l"(b) : "r"(addr));
}

// ---------------------------------------------------------------------------
// K0: weights -> [tap][split][c pad 112][ic pad 72] bf16 split
// ---------------------------------------------------------------------------
__global__ __launch_bounds__(256) void k0_wprep(const float* __restrict__ We) {
    int i = blockIdx.x * 256 + threadIdx.x;
    if (i >= 9 * 2 * 112 * 72) return;
    int tap = i / 16128, r = i % 16128;
    int s = r / 8064; r %= 8064;
    int c = r / 72, ic = r % 72;
    float v = (c < 100 && ic < 64) ? We[c * 576 + ic * 9 + tap] : 0.f;
    __nv_bfloat16 hi = __float2bfloat16(v);
    g_weP[i] = s ? __float2bfloat16(v - __bfloat162float(hi)) : hi;
}

// ---------------------------------------------------------------------------
// K1: 1x1 conv (256->64) + BN + SiLU -> bf16 split, pixel-major [b][pix][c]
// ---------------------------------------------------------------------------
__global__ __launch_bounds__(256) void k1_comp(
    const float* __restrict__ X, const float* __restrict__ Wc,
    const float* __restrict__ g1, const float* __restrict__ b1,
    const float* __restrict__ m1, const float* __restrict__ v1)
{
    const int b  = blockIdx.y;
    const int p0 = blockIdx.x * 64;

    __shared__ __align__(16) float Xs[32][68];
    __shared__ __align__(16) float Ws[32][68];
    __shared__ __align__(16) __nv_bfloat16 s_hi[64][72];
    __shared__ __align__(16) __nv_bfloat16 s_lo[64][72];

    const int tx = threadIdx.x & 15;
    const int ty = threadIdx.x >> 4;

    float acc[4][4];
#pragma unroll
    for (int i = 0; i < 4; i++)
#pragma unroll
        for (int j = 0; j < 4; j++) acc[i][j] = 0.f;

    const float* Xb = X + (size_t)b * CIN * (HH * WW) + p0;

    for (int k0 = 0; k0 < CIN; k0 += 32) {
        for (int i = threadIdx.x; i < 2048; i += 256) {
            int kk = i >> 6, nn = i & 63;
            Xs[kk][nn] = Xb[(size_t)(k0 + kk) * (HH * WW) + nn];
        }
        for (int i = threadIdx.x; i < 2048; i += 256) {
            int m = i >> 5, kk = i & 31;
            Ws[kk][m] = Wc[m * CIN + k0 + kk];
        }
        __syncthreads();
#pragma unroll
        for (int kk = 0; kk < 32; kk++) {
            float4 a  = *(const float4*)&Ws[kk][ty * 4];
            float4 bb = *(const float4*)&Xs[kk][tx * 4];
            float av[4] = {a.x, a.y, a.z, a.w};
            float bv[4] = {bb.x, bb.y, bb.z, bb.w};
#pragma unroll
            for (int i = 0; i < 4; i++)
#pragma unroll
                for (int j = 0; j < 4; j++) acc[i][j] += av[i] * bv[j];
        }
        __syncthreads();
    }

#pragma unroll
    for (int i = 0; i < 4; i++) {
        int m = ty * 4 + i;
        float is = g1[m] * rsqrtf(v1[m] + EPS);
        float bi = b1[m] - m1[m] * is;
#pragma unroll
        for (int j = 0; j < 4; j++) {
            float v = acc[i][j] * is + bi;
            float sv = v / (1.f + __expf(-v));
            __nv_bfloat16 hi = __float2bfloat16(sv);
            s_hi[tx * 4 + j][m] = hi;
            s_lo[tx * 4 + j][m] = __float2bfloat16(sv - __bfloat162float(hi));
        }
    }
    __syncthreads();

    for (int i = threadIdx.x; i < 1024; i += 256) {
        int bufi = i >> 9, r = (i >> 3) & 63, ch = i & 7;
        uint4 v = bufi ? *(const uint4*)&s_lo[r][ch * 8] : *(const uint4*)&s_hi[r][ch * 8];
        uint4* dst = (uint4*)(bufi ? g_midT_lo : g_midT_hi);
        dst[(size_t)(b * 6400 + p0 + r) * 8 + ch] = v;
    }
}

// ---------------------------------------------------------------------------
// K2: 3x3 conv (64->100) via mma.sync bf16 split-3 + BN + shuffle + softmax
// ---------------------------------------------------------------------------
#define SM_ACT_HI 0
#define SM_ACT_LO 25920
#define SM_W      51840
#define SM_SCS    84096
#define SM_BIS    84496
#define SM_TOTAL  84992
#define DT_STRIDE 122

__global__ __launch_bounds__(256, 2)
void k2_enc(const float* __restrict__ g2, const float* __restrict__ b2,
            const float* __restrict__ m2, const float* __restrict__ v2)
{
    extern __shared__ __align__(16) char sm[];
    const int b  = blockIdx.z;
    const int h0 = blockIdx.y * 16;
    const int w0 = blockIdx.x * 8;
    const int tid = threadIdx.x;
    const int wid = tid >> 5;
    const int lan = tid & 31;
    const uint32_t smb = smem_u32(sm);

    if (tid < 100) {
        float is = g2[tid] * rsqrtf(v2[tid] + EPS);
        ((float*)(sm + SM_SCS))[tid] = is;
        ((float*)(sm + SM_BIS))[tid] = b2[tid] - m2[tid] * is;
    }

    for (int k = tid; k < 2880; k += 256) {
        int bufi = (k >= 1440);
        int r = bufi ? k - 1440 : k;
        int row = r >> 3, ch = r & 7;
        int y = row / 10, x = row - y * 10;
        int gh = h0 + y - 1, gw = w0 + x - 1;
        uint4 v = make_uint4(0, 0, 0, 0);
        if (gh >= 0 && gh < HH && gw >= 0 && gw < WW) {
            const uint4* src = (const uint4*)(bufi ? g_midT_lo : g_midT_hi);
            v = src[(size_t)(b * 6400 + gh * WW + gw) * 8 + ch];
        }
        *(uint4*)(sm + (bufi ? SM_ACT_LO : SM_ACT_HI) + row * 144 + (ch << 4)) = v;
    }

    const int warpm = wid & 3;
    const int warpn = wid >> 2;

    float acc[2][7][4];
#pragma unroll
    for (int mb = 0; mb < 2; mb++)
#pragma unroll
        for (int nb = 0; nb < 7; nb++)
#pragma unroll
            for (int j = 0; j < 4; j++) acc[mb][nb][j] = 0.f;

    const int pA0 = warpm * 32 + (lan & 15);
    const int pyA0 = pA0 >> 3, pxA0 = pA0 & 7;
    const uint32_t a_half = (uint32_t)((lan >> 4) << 4);
    const int cB = warpn * 56 + (lan & 7);
    const uint32_t b_half = (uint32_t)(((lan >> 3) & 1) << 4);
    const uint32_t wb_hi = smb + SM_W + (uint32_t)cB * 144 + b_half;
    const uint32_t wb_lo = wb_hi + 16128;

    for (int tap = 0; tap < 9; tap++) {
        const int dy = tap / 3, dx = tap - dy * 3;
        __syncthreads();
        {
            const uint4* gsrc = (const uint4*)g_weP + tap * 2016;
            for (int k = tid; k < 2016; k += 256)
                *(uint4*)(sm + SM_W + (k << 4)) = gsrc[k];
        }
        __syncthreads();

        uint32_t arow0 = (uint32_t)(((pyA0 + dy) * 10 + pxA0 + dx) * 144) + a_half;
        uint32_t arow1 = (uint32_t)(((((pA0 + 16) >> 3) + dy) * 10 + ((pA0 + 16) & 7) + dx) * 144) + a_half;

#pragma unroll
        for (int ks = 0; ks < 4; ks++) {
            const uint32_t ko = (uint32_t)(ks << 5);
            uint32_t Ah[2][4], Al[2][4];
            ldsm_x4(Ah[0][0], Ah[0][1], Ah[0][2], Ah[0][3], smb + SM_ACT_HI + arow0 + ko);
            ldsm_x4(Ah[1][0], Ah[1][1], Ah[1][2], Ah[1][3], smb + SM_ACT_HI + arow1 + ko);
            ldsm_x4(Al[0][0], Al[0][1], Al[0][2], Al[0][3], smb + SM_ACT_LO + arow0 + ko);
            ldsm_x4(Al[1][0], Al[1][1], Al[1][2], Al[1][3], smb + SM_ACT_LO + arow1 + ko);
#pragma unroll
            for (int nb = 0; nb < 7; nb++) {
                uint32_t bh0, bh1, bl0, bl1;
                ldsm_x2(bh0, bh1, wb_hi + (uint32_t)(nb * 1152) + ko);
                ldsm_x2(bl0, bl1, wb_lo + (uint32_t)(nb * 1152) + ko);
#pragma unroll
                for (int mb = 0; mb < 2; mb++) {
                    mma16816(acc[mb][nb], Ah[mb], bh0, bh1);
                    mma16816(acc[mb][nb], Ah[mb], bl0, bl1);
                    mma16816(acc[mb][nb], Al[mb], bh0, bh1);
                }
            }
        }
    }
    __syncthreads();

    float* Dt = (float*)sm;
#pragma unroll
    for (int mb = 0; mb < 2; mb++) {
        int r = warpm * 32 + mb * 16 + (lan >> 2);
#pragma unroll
        for (int nb = 0; nb < 7; nb++) {
            int c = warpn * 56 + nb * 8 + 2 * (lan & 3);
            *(float2*)&Dt[r * DT_STRIDE + c] = make_float2(acc[mb][nb][0], acc[mb][nb][1]);
            *(float2*)&Dt[(r + 8) * DT_STRIDE + c] = make_float2(acc[mb][nb][2], acc[mb][nb][3]);
        }
    }
    __syncthreads();

    const float* scs = (const float*)(sm + SM_SCS);
    const float* bis = (const float*)(sm + SM_BIS);
    for (int it = tid; it < 512; it += 256) {
        int p = it >> 2, q = it & 3;
        float v[25];
        float mx = -1e30f;
#pragma unroll
        for (int k = 0; k < 25; k++) {
            int m = (k << 2) + q;
            float x = Dt[p * DT_STRIDE + m] * scs[m] + bis[m];
            v[k] = x;
            mx = fmaxf(mx, x);
        }
        float s = 0.f;
#pragma unroll
        for (int k = 0; k < 25; k++) {
            float e = __expf(v[k] - mx);
            v[k] = e;
            s += e;
        }
        float inv = 1.f / s;
        int y = 2 * (h0 + (p >> 3)) + (q >> 1);
        int x = 2 * (w0 + (p & 7)) + (q & 1);
#pragma unroll
        for (int k = 0; k < 25; k++)
            g_wm[(((size_t)(b * K2T + k)) * HO + y) * WO + x] = v[k] * inv;
    }
}

// ---------------------------------------------------------------------------
// K3 v3: thread = (pixel, subpixel). 4-lane smem broadcast of X across
// subpixels; 25 CARAFE weights in registers; f32x2 FMA; 4 u64 accumulators.
// ---------------------------------------------------------------------------
#define XST 36   // Xs float stride per position

__global__ __launch_bounds__(256, 4) void k3_carafe(
    const float* __restrict__ X, float* __restrict__ out)
{
    __shared__ __align__(16) float Xs[144 * XST];   // 20.7KB

    const int b = blockIdx.y;
    const int h0 = (blockIdx.x / 10) * 8;
    const int w0 = (blockIdx.x % 10) * 8;

    const int tid = threadIdx.x;
    const int wid = tid >> 5, lan = tid & 31;
    const int s = lan & 3;                 // subpixel
    const int w = lan >> 2;                // px col within tile row (warp owns row h=wid)
    const int h = wid;
    const int si = s >> 1, sj = s & 1;
    const int y0 = 2 * (h0 + h) + si, x0 = 2 * (w0 + w) + sj;

    // 25 weights for this (pixel, subpixel) in registers; coalesced LDG
    float wreg[25];
#pragma unroll
    for (int t = 0; t < 25; t++)
        wreg[t] = g_wm[(((size_t)(b * K2T + t)) * HO + y0) * WO + x0];

    const uint32_t xpix = smem_u32(Xs) + (uint32_t)((h * 12 + w) * XST * 4);
    float* const obase = out + ((size_t)b * CIN * HO + (size_t)y0) * WO + x0;

    for (int cg = 0; cg < 8; cg++) {
        __syncthreads();   // previous cg's reads done
        // stage 32 ch x 144 pos, channel-fastest
        for (int i = tid; i < 4608; i += 256) {
            int cc = i / 144, r = i - cc * 144;
            int dy = r / 12, dx = r - dy * 12;
            int gh = h0 + dy - 2, gw = w0 + dx - 2;
            float val = 0.f;
            if (gh >= 0 && gh < HH && gw >= 0 && gw < WW)
                val = X[(((size_t)(b * CIN + cg * 32 + cc)) * HH + gh) * WW + gw];
            Xs[r * XST + cc] = val;
        }
        __syncthreads();

#pragma unroll
        for (int cs = 0; cs < 4; cs++) {
            const uint32_t xb = xpix + (uint32_t)(cs * 32);
            uint64_t acc0 = 0, acc1 = 0, acc2 = 0, acc3 = 0;
#pragma unroll
            for (int t = 0; t < 25; t++) {
                const int ki = t / 5, kj = t - ki * 5;
                const uint32_t off = (uint32_t)((ki * 12 + kj) * XST * 4);
                uint64_t w2 = bcast2(wreg[t]);
                uint64_t xp0, xp1, xp2, xp3;
                lds_v2u64(xp0, xp1, xb + off);
                lds_v2u64(xp2, xp3, xb + off + 16);
                fma2(acc0, xp0, w2);
                fma2(acc1, xp1, w2);
                fma2(acc2, xp2, w2);
                fma2(acc3, xp3, w2);
            }
            float* ob = obase + (size_t)(cg * 32 + cs * 8) * (HO * WO);
            float va, vb;
            unpack2(va, vb, acc0);
            ob[0] = va; ob[HO * WO] = vb;
            unpack2(va, vb, acc1);
            ob[2 * HO * WO] = va; ob[3 * HO * WO] = vb;
            unpack2(va, vb, acc2);
            ob[4 * HO * WO] = va; ob[5 * HO * WO] = vb;
            unpack2(va, vb, acc3);
            ob[6 * HO * WO] = va; ob[7 * HO * WO] = vb;
        }
    }
}

// ---------------------------------------------------------------------------
extern "C" void kernel_launch(void* const* d_in, const int* in_sizes, int n_in,
                              void* d_out, int out_size)
{
    const float* X  = (const float*)d_in[0];
    const float* Wc = (const float*)d_in[1];
    const float* g1 = (const float*)d_in[2];
    const float* b1 = (const float*)d_in[3];
    const float* m1 = (const float*)d_in[4];
    const float* v1 = (const float*)d_in[5];
    const float* We = (const float*)d_in[6];
    const float* g2 = (const float*)d_in[7];
    const float* b2 = (const float*)d_in[8];
    const float* m2 = (const float*)d_in[9];
    const float* v2 = (const float*)d_in[10];
    float* out = (float*)d_out;

    cudaFuncSetAttribute(k2_enc, cudaFuncAttributeMaxDynamicSharedMemorySize, SM_TOTAL);

    k0_wprep<<<568, 256>>>(We);
    k1_comp<<<dim3(100, BATCH), 256>>>(X, Wc, g1, b1, m1, v1);
    k2_enc<<<dim3(10, 5, BATCH), 256, SM_TOTAL>>>(g2, b2, m2, v2);
    k3_carafe<<<dim3(100, BATCH), 256>>>(X, out);
}

// round 6
// speedup vs baseline: 1.2685x; 1.1096x over previous
#include <cuda_runtime.h>
#include <cuda_bf16.h>
#include <cstdint>

#define BATCH 16
#define CIN   256
#define HH    80
#define WW    80
#define CMID  64
#define K2T   25
#define HO    160
#define WO    160
#define EPS   1e-5f

// ---------------------------------------------------------------------------
// Device scratch (allocation-free)
// ---------------------------------------------------------------------------
__device__ __align__(16) __nv_bfloat16 g_midT_hi[(size_t)BATCH * 6400 * 64]; // [b][pix][c]
__device__ __align__(16) __nv_bfloat16 g_midT_lo[(size_t)BATCH * 6400 * 64];
__device__ __align__(16) __nv_bfloat16 g_weP[9 * 2 * 112 * 72];
__device__ __align__(16) float g_wm[(size_t)BATCH * K2T * HO * WO];
__device__ __align__(16) float g_xT[(size_t)BATCH * 6400 * 256];   // X pixel-major, 105MB

__device__ __forceinline__ uint32_t smem_u32(const void* p) {
    uint32_t a;
    asm("{ .reg .u64 t; cvta.to.shared.u64 t, %1; cvt.u32.u64 %0, t; }" : "=r"(a) : "l"(p));
    return a;
}
__device__ __forceinline__ void ldsm_x4(uint32_t& r0, uint32_t& r1, uint32_t& r2, uint32_t& r3,
                                        uint32_t addr) {
    asm volatile("ldmatrix.sync.aligned.m8n8.x4.shared.b16 {%0,%1,%2,%3}, [%4];"
                 : "=r"(r0), "=r"(r1), "=r"(r2), "=r"(r3) : "r"(addr));
}
__device__ __forceinline__ void ldsm_x2(uint32_t& r0, uint32_t& r1, uint32_t addr) {
    asm volatile("ldmatrix.sync.aligned.m8n8.x2.shared.b16 {%0,%1}, [%2];"
                 : "=r"(r0), "=r"(r1) : "r"(addr));
}
__device__ __forceinline__ void mma16816(float* d, const uint32_t* a, uint32_t b0, uint32_t b1) {
    asm volatile(
        "mma.sync.aligned.m16n8k16.row.col.f32.bf16.bf16.f32 "
        "{%0,%1,%2,%3}, {%4,%5,%6,%7}, {%8,%9}, {%0,%1,%2,%3};"
        : "+f"(d[0]), "+f"(d[1]), "+f"(d[2]), "+f"(d[3])
        : "r"(a[0]), "r"(a[1]), "r"(a[2]), "r"(a[3]), "r"(b0), "r"(b1));
}
// Packed fp32 helpers (Blackwell f32x2 pipe)
__device__ __forceinline__ void fma2(uint64_t& d, uint64_t a, uint64_t b) {
    asm("fma.rn.f32x2 %0, %1, %2, %0;" : "+l"(d) : "l"(a), "l"(b));
}
__device__ __forceinline__ uint64_t bcast2(float x) {
    uint64_t r;
    asm("mov.b64 %0, {%1, %1};" : "=l"(r) : "f"(x));
    return r;
}
__device__ __forceinline__ void unpack2(float& lo, float& hi, uint64_t v) {
    asm("mov.b64 {%0, %1}, %2;" : "=f"(lo), "=f"(hi) : "l"(v));
}
__device__ __forceinline__ void lds_v2u64(uint64_t& a, uint64_t& b, uint32_t addr) {
    asm volatile("ld.shared.v2.u64 {%0, %1}, [%2];" : "=l"(a), "=l"(b) : "r"(addr));
}
__device__ __forceinline__ void cp_async16(uint32_t saddr, const void* gptr, uint32_t sz) {
    asm volatile("cp.async.cg.shared.global [%0], [%1], 16, %2;"
                 :: "r"(saddr), "l"(gptr), "r"(sz) : "memory");
}

// ---------------------------------------------------------------------------
// K0: conv2 weights -> [tap][split][c pad 112][ic pad 72] bf16 split
// ---------------------------------------------------------------------------
__global__ __launch_bounds__(256) void k0_wprep(const float* __restrict__ We) {
    int i = blockIdx.x * 256 + threadIdx.x;
    if (i >= 9 * 2 * 112 * 72) return;
    int tap = i / 16128, r = i % 16128;
    int s = r / 8064; r %= 8064;
    int c = r / 72, ic = r % 72;
    float v = (c < 100 && ic < 64) ? We[c * 576 + ic * 9 + tap] : 0.f;
    __nv_bfloat16 hi = __float2bfloat16(v);
    g_weP[i] = s ? __float2bfloat16(v - __bfloat162float(hi)) : hi;
}

// ---------------------------------------------------------------------------
// K0x: transpose X (b, c, p) -> g_xT (b, p, c). 32x32 tiles via smem.
// ---------------------------------------------------------------------------
__global__ __launch_bounds__(256) void k0x_transpose(const float* __restrict__ X) {
    __shared__ float t[32][33];
    const int b = blockIdx.z;
    const int p0 = blockIdx.x * 32, c0 = blockIdx.y * 32;
    const int tx = threadIdx.x & 31, ty = threadIdx.x >> 5;
    const float* src = X + ((size_t)b * 256 + c0) * 6400 + p0;
#pragma unroll
    for (int r = 0; r < 4; r++)
        t[ty + 8 * r][tx] = src[(size_t)(ty + 8 * r) * 6400 + tx];
    __syncthreads();
    float* dst = g_xT + ((size_t)b * 6400 + p0) * 256 + c0;
#pragma unroll
    for (int r = 0; r < 4; r++)
        dst[(size_t)(ty + 8 * r) * 256 + tx] = t[tx][ty + 8 * r];
}

// ---------------------------------------------------------------------------
// K1: 1x1 conv (256->64) + BN + SiLU -> bf16 split, pixel-major [b][pix][c]
// ---------------------------------------------------------------------------
__global__ __launch_bounds__(256) void k1_comp(
    const float* __restrict__ X, const float* __restrict__ Wc,
    const float* __restrict__ g1, const float* __restrict__ b1,
    const float* __restrict__ m1, const float* __restrict__ v1)
{
    const int b  = blockIdx.y;
    const int p0 = blockIdx.x * 64;

    __shared__ __align__(16) float Xs[32][68];
    __shared__ __align__(16) float Ws[32][68];
    __shared__ __align__(16) __nv_bfloat16 s_hi[64][72];
    __shared__ __align__(16) __nv_bfloat16 s_lo[64][72];

    const int tx = threadIdx.x & 15;
    const int ty = threadIdx.x >> 4;

    float acc[4][4];
#pragma unroll
    for (int i = 0; i < 4; i++)
#pragma unroll
        for (int j = 0; j < 4; j++) acc[i][j] = 0.f;

    const float* Xb = X + (size_t)b * CIN * (HH * WW) + p0;

    for (int k0 = 0; k0 < CIN; k0 += 32) {
        for (int i = threadIdx.x; i < 2048; i += 256) {
            int kk = i >> 6, nn = i & 63;
            Xs[kk][nn] = Xb[(size_t)(k0 + kk) * (HH * WW) + nn];
        }
        for (int i = threadIdx.x; i < 2048; i += 256) {
            int m = i >> 5, kk = i & 31;
            Ws[kk][m] = Wc[m * CIN + k0 + kk];
        }
        __syncthreads();
#pragma unroll
        for (int kk = 0; kk < 32; kk++) {
            float4 a  = *(const float4*)&Ws[kk][ty * 4];
            float4 bb = *(const float4*)&Xs[kk][tx * 4];
            float av[4] = {a.x, a.y, a.z, a.w};
            float bv[4] = {bb.x, bb.y, bb.z, bb.w};
#pragma unroll
            for (int i = 0; i < 4; i++)
#pragma unroll
                for (int j = 0; j < 4; j++) acc[i][j] += av[i] * bv[j];
        }
        __syncthreads();
    }

#pragma unroll
    for (int i = 0; i < 4; i++) {
        int m = ty * 4 + i;
        float is = g1[m] * rsqrtf(v1[m] + EPS);
        float bi = b1[m] - m1[m] * is;
#pragma unroll
        for (int j = 0; j < 4; j++) {
            float v = acc[i][j] * is + bi;
            float sv = v / (1.f + __expf(-v));
            __nv_bfloat16 hi = __float2bfloat16(sv);
            s_hi[tx * 4 + j][m] = hi;
            s_lo[tx * 4 + j][m] = __float2bfloat16(sv - __bfloat162float(hi));
        }
    }
    __syncthreads();

    for (int i = threadIdx.x; i < 1024; i += 256) {
        int bufi = i >> 9, r = (i >> 3) & 63, ch = i & 7;
        uint4 v = bufi ? *(const uint4*)&s_lo[r][ch * 8] : *(const uint4*)&s_hi[r][ch * 8];
        uint4* dst = (uint4*)(bufi ? g_midT_lo : g_midT_hi);
        dst[(size_t)(b * 6400 + p0 + r) * 8 + ch] = v;
    }
}

// ---------------------------------------------------------------------------
// K2: 3x3 conv (64->100) via mma.sync bf16 split-3 + BN + shuffle + softmax
// ---------------------------------------------------------------------------
#define SM_ACT_HI 0
#define SM_ACT_LO 25920
#define SM_W      51840
#define SM_SCS    84096
#define SM_BIS    84496
#define SM_TOTAL  84992
#define DT_STRIDE 122

__global__ __launch_bounds__(256, 2)
void k2_enc(const float* __restrict__ g2, const float* __restrict__ b2,
            const float* __restrict__ m2, const float* __restrict__ v2)
{
    extern __shared__ __align__(16) char sm[];
    const int b  = blockIdx.z;
    const int h0 = blockIdx.y * 16;
    const int w0 = blockIdx.x * 8;
    const int tid = threadIdx.x;
    const int wid = tid >> 5;
    const int lan = tid & 31;
    const uint32_t smb = smem_u32(sm);

    if (tid < 100) {
        float is = g2[tid] * rsqrtf(v2[tid] + EPS);
        ((float*)(sm + SM_SCS))[tid] = is;
        ((float*)(sm + SM_BIS))[tid] = b2[tid] - m2[tid] * is;
    }

    for (int k = tid; k < 2880; k += 256) {
        int bufi = (k >= 1440);
        int r = bufi ? k - 1440 : k;
        int row = r >> 3, ch = r & 7;
        int y = row / 10, x = row - y * 10;
        int gh = h0 + y - 1, gw = w0 + x - 1;
        uint4 v = make_uint4(0, 0, 0, 0);
        if (gh >= 0 && gh < HH && gw >= 0 && gw < WW) {
            const uint4* src = (const uint4*)(bufi ? g_midT_lo : g_midT_hi);
            v = src[(size_t)(b * 6400 + gh * WW + gw) * 8 + ch];
        }
        *(uint4*)(sm + (bufi ? SM_ACT_LO : SM_ACT_HI) + row * 144 + (ch << 4)) = v;
    }

    const int warpm = wid & 3;
    const int warpn = wid >> 2;

    float acc[2][7][4];
#pragma unroll
    for (int mb = 0; mb < 2; mb++)
#pragma unroll
        for (int nb = 0; nb < 7; nb++)
#pragma unroll
            for (int j = 0; j < 4; j++) acc[mb][nb][j] = 0.f;

    const int pA0 = warpm * 32 + (lan & 15);
    const int pyA0 = pA0 >> 3, pxA0 = pA0 & 7;
    const uint32_t a_half = (uint32_t)((lan >> 4) << 4);
    const int cB = warpn * 56 + (lan & 7);
    const uint32_t b_half = (uint32_t)(((lan >> 3) & 1) << 4);
    const uint32_t wb_hi = smb + SM_W + (uint32_t)cB * 144 + b_half;
    const uint32_t wb_lo = wb_hi + 16128;

    for (int tap = 0; tap < 9; tap++) {
        const int dy = tap / 3, dx = tap - dy * 3;
        __syncthreads();
        {
            const uint4* gsrc = (const uint4*)g_weP + tap * 2016;
            for (int k = tid; k < 2016; k += 256)
                *(uint4*)(sm + SM_W + (k << 4)) = gsrc[k];
        }
        __syncthreads();

        uint32_t arow0 = (uint32_t)(((pyA0 + dy) * 10 + pxA0 + dx) * 144) + a_half;
        uint32_t arow1 = (uint32_t)(((((pA0 + 16) >> 3) + dy) * 10 + ((pA0 + 16) & 7) + dx) * 144) + a_half;

#pragma unroll
        for (int ks = 0; ks < 4; ks++) {
            const uint32_t ko = (uint32_t)(ks << 5);
            uint32_t Ah[2][4], Al[2][4];
            ldsm_x4(Ah[0][0], Ah[0][1], Ah[0][2], Ah[0][3], smb + SM_ACT_HI + arow0 + ko);
            ldsm_x4(Ah[1][0], Ah[1][1], Ah[1][2], Ah[1][3], smb + SM_ACT_HI + arow1 + ko);
            ldsm_x4(Al[0][0], Al[0][1], Al[0][2], Al[0][3], smb + SM_ACT_LO + arow0 + ko);
            ldsm_x4(Al[1][0], Al[1][1], Al[1][2], Al[1][3], smb + SM_ACT_LO + arow1 + ko);
#pragma unroll
            for (int nb = 0; nb < 7; nb++) {
                uint32_t bh0, bh1, bl0, bl1;
                ldsm_x2(bh0, bh1, wb_hi + (uint32_t)(nb * 1152) + ko);
                ldsm_x2(bl0, bl1, wb_lo + (uint32_t)(nb * 1152) + ko);
#pragma unroll
                for (int mb = 0; mb < 2; mb++) {
                    mma16816(acc[mb][nb], Ah[mb], bh0, bh1);
                    mma16816(acc[mb][nb], Ah[mb], bl0, bl1);
                    mma16816(acc[mb][nb], Al[mb], bh0, bh1);
                }
            }
        }
    }
    __syncthreads();

    float* Dt = (float*)sm;
#pragma unroll
    for (int mb = 0; mb < 2; mb++) {
        int r = warpm * 32 + mb * 16 + (lan >> 2);
#pragma unroll
        for (int nb = 0; nb < 7; nb++) {
            int c = warpn * 56 + nb * 8 + 2 * (lan & 3);
            *(float2*)&Dt[r * DT_STRIDE + c] = make_float2(acc[mb][nb][0], acc[mb][nb][1]);
            *(float2*)&Dt[(r + 8) * DT_STRIDE + c] = make_float2(acc[mb][nb][2], acc[mb][nb][3]);
        }
    }
    __syncthreads();

    const float* scs = (const float*)(sm + SM_SCS);
    const float* bis = (const float*)(sm + SM_BIS);
    for (int it = tid; it < 512; it += 256) {
        int p = it >> 2, q = it & 3;
        float v[25];
        float mx = -1e30f;
#pragma unroll
        for (int k = 0; k < 25; k++) {
            int m = (k << 2) + q;
            float x = Dt[p * DT_STRIDE + m] * scs[m] + bis[m];
            v[k] = x;
            mx = fmaxf(mx, x);
        }
        float s = 0.f;
#pragma unroll
        for (int k = 0; k < 25; k++) {
            float e = __expf(v[k] - mx);
            v[k] = e;
            s += e;
        }
        float inv = 1.f / s;
        int y = 2 * (h0 + (p >> 3)) + (q >> 1);
        int x = 2 * (w0 + (p & 7)) + (q & 1);
#pragma unroll
        for (int k = 0; k < 25; k++)
            g_wm[(((size_t)(b * K2T + k)) * HO + y) * WO + x] = v[k] * inv;
    }
}

// ---------------------------------------------------------------------------
// K3 v4: thread = (pixel, ch-group-of-8), all 4 subpixels per thread.
// X from g_xT via double-buffered cp.async; weights smem-broadcast; f32x2 FMA.
// ---------------------------------------------------------------------------
#define XST 36                   // floats per position row (144B)
#define K3_WS   0                // Ws4[25][64][4] floats = 25600B
#define K3_XS0  25600            // 144*36*4 = 20736B
#define K3_XS1  46336
#define K3_SMEM 67072

__global__ __launch_bounds__(256, 3) void k3_carafe(float* __restrict__ out)
{
    extern __shared__ __align__(16) char sm3[];
    float* Ws4 = (float*)(sm3 + K3_WS);

    const int b = blockIdx.y;
    const int h0 = (blockIdx.x / 10) * 8;
    const int w0 = (blockIdx.x % 10) * 8;
    const int tid = threadIdx.x;

    // CARAFE weights for this tile -> Ws4[t][px][s]
    for (int i = tid; i < 3200; i += 256) {
        int kk = i >> 7, r = i & 127, si = r >> 6, p = r & 63;
        int hh = p >> 3, ww = p & 7;
        int y = 2 * (h0 + hh) + si, x = 2 * (w0 + ww);
        float2 v = *(const float2*)&g_wm[(((size_t)(b * K2T + kk)) * HO + y) * WO + x];
        Ws4[(kk * 64 + p) * 4 + si * 2 + 0] = v.x;
        Ws4[(kk * 64 + p) * 4 + si * 2 + 1] = v.y;
    }

    const float* Xb = g_xT + (size_t)b * 6400 * 256;

#define K3_STAGE(cgx, bufoff) do {                                               \
        for (int i = tid; i < 1152; i += 256) {                                  \
            int pos = i >> 3, c16 = i & 7;                                       \
            int dy = pos / 12, dx = pos - dy * 12;                               \
            int gh = h0 + dy - 2, gw = w0 + dx - 2;                              \
            bool ok = (gh >= 0 && gh < HH && gw >= 0 && gw < WW);                \
            const float* src = Xb + (size_t)(ok ? (gh * WW + gw) : 0) * 256      \
                               + (cgx) * 32 + c16 * 4;                           \
            cp_async16(smem_u32(sm3 + (bufoff)) + (uint32_t)((pos * XST + c16 * 4) * 4), \
                       src, ok ? 16u : 0u);                                      \
        }                                                                        \
        asm volatile("cp.async.commit_group;" ::: "memory");                     \
    } while (0)

    K3_STAGE(0, K3_XS0);
    K3_STAGE(1, K3_XS1);

    const int px = tid >> 2, cg4 = tid & 3;
    const int h = px >> 3, w = px & 7;
    const uint32_t xoff = (uint32_t)(((h * 12 + w) * XST + cg4 * 8) * 4);
    const uint32_t wbase = smem_u32(sm3) + (uint32_t)(px * 16);
    const int y0 = 2 * (h0 + h), x0 = 2 * (w0 + w);

    for (int cg = 0; cg < 8; cg++) {
        if (cg < 7) asm volatile("cp.async.wait_group 1;" ::: "memory");
        else        asm volatile("cp.async.wait_group 0;" ::: "memory");
        __syncthreads();

        const uint32_t xb = smem_u32(sm3) + (uint32_t)((cg & 1) ? K3_XS1 : K3_XS0) + xoff;
        uint64_t acc[4][4];
#pragma unroll
        for (int s = 0; s < 4; s++)
#pragma unroll
            for (int k = 0; k < 4; k++) acc[s][k] = 0ull;

#pragma unroll
        for (int t = 0; t < 25; t++) {
            const int ki = t / 5, kj = t - ki * 5;
            const uint32_t off = (uint32_t)((ki * 12 + kj) * XST * 4);
            float4 wv;
            asm volatile("ld.shared.v4.f32 {%0,%1,%2,%3}, [%4];"
                         : "=f"(wv.x), "=f"(wv.y), "=f"(wv.z), "=f"(wv.w)
                         : "r"(wbase + (uint32_t)(t * 1024)));
            uint64_t w20 = bcast2(wv.x), w21 = bcast2(wv.y);
            uint64_t w22 = bcast2(wv.z), w23 = bcast2(wv.w);
            uint64_t xq0, xq1, xq2, xq3;
            lds_v2u64(xq0, xq1, xb + off);
            lds_v2u64(xq2, xq3, xb + off + 16);
            fma2(acc[0][0], xq0, w20); fma2(acc[0][1], xq1, w20);
            fma2(acc[0][2], xq2, w20); fma2(acc[0][3], xq3, w20);
            fma2(acc[1][0], xq0, w21); fma2(acc[1][1], xq1, w21);
            fma2(acc[1][2], xq2, w21); fma2(acc[1][3], xq3, w21);
            fma2(acc[2][0], xq0, w22); fma2(acc[2][1], xq1, w22);
            fma2(acc[2][2], xq2, w22); fma2(acc[2][3], xq3, w22);
            fma2(acc[3][0], xq0, w23); fma2(acc[3][1], xq1, w23);
            fma2(acc[3][2], xq2, w23); fma2(acc[3][3], xq3, w23);
        }
        __syncthreads();   // all reads of this buffer done before restaging

        float* ob = out + (((size_t)(b * CIN + cg * 32 + cg4 * 8)) * HO + y0) * WO + x0;
#pragma unroll
        for (int k = 0; k < 4; k++) {
            float s0a, s0b, s1a, s1b, s2a, s2b, s3a, s3b;
            unpack2(s0a, s0b, acc[0][k]);
            unpack2(s1a, s1b, acc[1][k]);
            unpack2(s2a, s2b, acc[2][k]);
            unpack2(s3a, s3b, acc[3][k]);
            float* p0 = ob + (size_t)(2 * k) * (HO * WO);
            float* p1 = p0 + HO * WO;
            *(float2*)p0        = make_float2(s0a, s1a);
            *(float2*)(p0 + WO) = make_float2(s2a, s3a);
            *(float2*)p1        = make_float2(s0b, s1b);
            *(float2*)(p1 + WO) = make_float2(s2b, s3b);
        }

        if (cg + 2 < 8) {
            if ((cg & 1) == 0) K3_STAGE(cg + 2, K3_XS0);
            else               K3_STAGE(cg + 2, K3_XS1);
        }
    }
}

// ---------------------------------------------------------------------------
extern "C" void kernel_launch(void* const* d_in, const int* in_sizes, int n_in,
                              void* d_out, int out_size)
{
    const float* X  = (const float*)d_in[0];
    const float* Wc = (const float*)d_in[1];
    const float* g1 = (const float*)d_in[2];
    const float* b1 = (const float*)d_in[3];
    const float* m1 = (const float*)d_in[4];
    const float* v1 = (const float*)d_in[5];
    const float* We = (const float*)d_in[6];
    const float* g2 = (const float*)d_in[7];
    const float* b2 = (const float*)d_in[8];
    const float* m2 = (const float*)d_in[9];
    const float* v2 = (const float*)d_in[10];
    float* out = (float*)d_out;

    cudaFuncSetAttribute(k2_enc, cudaFuncAttributeMaxDynamicSharedMemorySize, SM_TOTAL);
    cudaFuncSetAttribute(k3_carafe, cudaFuncAttributeMaxDynamicSharedMemorySize, K3_SMEM);

    k0_wprep<<<568, 256>>>(We);
    k0x_transpose<<<dim3(200, 8, BATCH), 256>>>(X);
    k1_comp<<<dim3(100, BATCH), 256>>>(X, Wc, g1, b1, m1, v1);
    k2_enc<<<dim3(10, 5, BATCH), 256, SM_TOTAL>>>(g2, b2, m2, v2);
    k3_carafe<<<dim3(100, BATCH), 256, K3_SMEM>>>(out);
}

// round 7
// speedup vs baseline: 1.4558x; 1.1477x over previous
#include <cuda_runtime.h>
#include <cuda_bf16.h>
#include <cstdint>

#define BATCH 16
#define CIN   256
#define HH    80
#define WW    80
#define CMID  64
#define K2T   25
#define HO    160
#define WO    160
#define EPS   1e-5f

// ---------------------------------------------------------------------------
// Device scratch (allocation-free)
// ---------------------------------------------------------------------------
__device__ __align__(16) __nv_bfloat16 g_midT_hi[(size_t)BATCH * 6400 * 64]; // [b][pix][c]
__device__ __align__(16) __nv_bfloat16 g_midT_lo[(size_t)BATCH * 6400 * 64];
__device__ __align__(16) __nv_bfloat16 g_weP[9 * 2 * 112 * 72];
__device__ __align__(16) float g_wm[(size_t)BATCH * K2T * HO * WO];
__device__ __align__(16) float g_xT[(size_t)BATCH * 6400 * 256];   // X pixel-major, 105MB

__device__ __forceinline__ uint32_t smem_u32(const void* p) {
    uint32_t a;
    asm("{ .reg .u64 t; cvta.to.shared.u64 t, %1; cvt.u32.u64 %0, t; }" : "=r"(a) : "l"(p));
    return a;
}
__device__ __forceinline__ void ldsm_x4(uint32_t& r0, uint32_t& r1, uint32_t& r2, uint32_t& r3,
                                        uint32_t addr) {
    asm volatile("ldmatrix.sync.aligned.m8n8.x4.shared.b16 {%0,%1,%2,%3}, [%4];"
                 : "=r"(r0), "=r"(r1), "=r"(r2), "=r"(r3) : "r"(addr));
}
__device__ __forceinline__ void ldsm_x2(uint32_t& r0, uint32_t& r1, uint32_t addr) {
    asm volatile("ldmatrix.sync.aligned.m8n8.x2.shared.b16 {%0,%1}, [%2];"
                 : "=r"(r0), "=r"(r1) : "r"(addr));
}
__device__ __forceinline__ void ldsm_x2t(uint32_t& r0, uint32_t& r1, uint32_t addr) {
    asm volatile("ldmatrix.sync.aligned.m8n8.x2.trans.shared.b16 {%0,%1}, [%2];"
                 : "=r"(r0), "=r"(r1) : "r"(addr));
}
__device__ __forceinline__ void mma16816(float* d, const uint32_t* a, uint32_t b0, uint32_t b1) {
    asm volatile(
        "mma.sync.aligned.m16n8k16.row.col.f32.bf16.bf16.f32 "
        "{%0,%1,%2,%3}, {%4,%5,%6,%7}, {%8,%9}, {%0,%1,%2,%3};"
        : "+f"(d[0]), "+f"(d[1]), "+f"(d[2]), "+f"(d[3])
        : "r"(a[0]), "r"(a[1]), "r"(a[2]), "r"(a[3]), "r"(b0), "r"(b1));
}
// Packed fp32 helpers (Blackwell f32x2 pipe)
__device__ __forceinline__ void fma2(uint64_t& d, uint64_t a, uint64_t b) {
    asm("fma.rn.f32x2 %0, %1, %2, %0;" : "+l"(d) : "l"(a), "l"(b));
}
__device__ __forceinline__ uint64_t bcast2(float x) {
    uint64_t r;
    asm("mov.b64 %0, {%1, %1};" : "=l"(r) : "f"(x));
    return r;
}
__device__ __forceinline__ void unpack2(float& lo, float& hi, uint64_t v) {
    asm("mov.b64 {%0, %1}, %2;" : "=f"(lo), "=f"(hi) : "l"(v));
}
__device__ __forceinline__ void lds_v2u64(uint64_t& a, uint64_t& b, uint32_t addr) {
    asm volatile("ld.shared.v2.u64 {%0, %1}, [%2];" : "=l"(a), "=l"(b) : "r"(addr));
}
__device__ __forceinline__ void cp_async16(uint32_t saddr, const void* gptr, uint32_t sz) {
    asm volatile("cp.async.cg.shared.global [%0], [%1], 16, %2;"
                 :: "r"(saddr), "l"(gptr), "r"(sz) : "memory");
}

// ---------------------------------------------------------------------------
// K0: conv2 weights -> [tap][split][c pad 112][ic pad 72] bf16 split
// ---------------------------------------------------------------------------
__global__ __launch_bounds__(256) void k0_wprep(const float* __restrict__ We) {
    int i = blockIdx.x * 256 + threadIdx.x;
    if (i >= 9 * 2 * 112 * 72) return;
    int tap = i / 16128, r = i % 16128;
    int s = r / 8064; r %= 8064;
    int c = r / 72, ic = r % 72;
    float v = (c < 100 && ic < 64) ? We[c * 576 + ic * 9 + tap] : 0.f;
    __nv_bfloat16 hi = __float2bfloat16(v);
    g_weP[i] = s ? __float2bfloat16(v - __bfloat162float(hi)) : hi;
}

// ---------------------------------------------------------------------------
// K0x: transpose X (b, c, p) -> g_xT (b, p, c). 32x32 tiles via smem.
// ---------------------------------------------------------------------------
__global__ __launch_bounds__(256) void k0x_transpose(const float* __restrict__ X) {
    __shared__ float t[32][33];
    const int b = blockIdx.z;
    const int p0 = blockIdx.x * 32, c0 = blockIdx.y * 32;
    const int tx = threadIdx.x & 31, ty = threadIdx.x >> 5;
    const float* src = X + ((size_t)b * 256 + c0) * 6400 + p0;
#pragma unroll
    for (int r = 0; r < 4; r++)
        t[ty + 8 * r][tx] = src[(size_t)(ty + 8 * r) * 6400 + tx];
    __syncthreads();
    float* dst = g_xT + ((size_t)b * 6400 + p0) * 256 + c0;
#pragma unroll
    for (int r = 0; r < 4; r++)
        dst[(size_t)(ty + 8 * r) * 256 + tx] = t[tx][ty + 8 * r];
}

// ---------------------------------------------------------------------------
// K1 v2: 1x1 conv (256->64) via mma.sync bf16 split-3 + BN + SiLU.
// A = weights [64ch x 256k] (resident in smem, non-trans ldmatrix),
// B = X chunk [32k x 128px] (px-contiguous rows, trans ldmatrix),
// register-prefetch pipeline over 8 k-chunks. Output g_midT hi/lo [px][ch].
// ---------------------------------------------------------------------------
#define K1_SW    0            // weights hi [64][528B] = 33792; lo at +33792
#define K1_SXS   67584        // X chunk [split][32k][272B] = 8704*2
#define K1_SBN   84992        // scs 256B + bis 256B
#define K1_SMEM  85504
#define K1_DT    0            // epilogue [split][128px][144B], reuses weights

__global__ __launch_bounds__(256, 2) void k1_comp(
    const float* __restrict__ X, const float* __restrict__ Wc,
    const float* __restrict__ g1, const float* __restrict__ b1,
    const float* __restrict__ m1, const float* __restrict__ v1)
{
    extern __shared__ __align__(16) char sm1[];
    const int b   = blockIdx.y;
    const int px0 = blockIdx.x * 128;
    const int tid = threadIdx.x;
    const int wid = tid >> 5, lan = tid & 31;
    const uint32_t smb = smem_u32(sm1);

    // stage weights (bf16 split) - resident for whole CTA
    __nv_bfloat16* Wh = (__nv_bfloat16*)(sm1 + K1_SW);
    __nv_bfloat16* Wl = Wh + 16896;     // +33792B
    for (int i = tid; i < 16384; i += 256) {
        int m = i >> 8, k = i & 255;
        float v = Wc[i];
        __nv_bfloat16 hi = __float2bfloat16(v);
        Wh[m * 264 + k] = hi;
        Wl[m * 264 + k] = __float2bfloat16(v - __bfloat162float(hi));
    }
    float* scs = (float*)(sm1 + K1_SBN);
    float* bis = scs + 64;
    if (tid < 64) {
        float is = g1[tid] * rsqrtf(v1[tid] + EPS);
        scs[tid] = is;
        bis[tid] = b1[tid] - m1[tid] * is;
    }

    const float* Xb = X + (size_t)b * 256 * 6400 + px0;
    __nv_bfloat16* Xh = (__nv_bfloat16*)(sm1 + K1_SXS);
    __nv_bfloat16* Xl = Xh + 4352;      // +8704B

    // prefetch chunk 0
    float xp[16];
#pragma unroll
    for (int j = 0; j < 16; j++) {
        int e = j * 256 + tid;
        xp[j] = Xb[(size_t)(e >> 7) * 6400 + (e & 127)];
    }

    const int warpm = wid & 1;   // 2 warps in M (32 ch each)
    const int warpn = wid >> 1;  // 4 warps in N (32 px each)

    float acc[2][4][4];
#pragma unroll
    for (int mb = 0; mb < 2; mb++)
#pragma unroll
        for (int nb = 0; nb < 4; nb++)
#pragma unroll
            for (int j = 0; j < 4; j++) acc[mb][nb][j] = 0.f;

    // fragment address bases
    const uint32_t a_row = (uint32_t)(warpm * 32 + (lan & 15));
    const uint32_t a_half = (uint32_t)((lan >> 4) << 4);
    const uint32_t aw_hi = smb + K1_SW + a_row * 528 + a_half;
    const uint32_t aw_lo = aw_hi + 33792;
    const uint32_t b_base = smb + K1_SXS + (uint32_t)((lan & 15) * 272 + warpn * 64);

#pragma unroll 1
    for (int cg = 0; cg < 8; cg++) {
        // store staged chunk (px-contiguous 2B stores: conflict-free)
#pragma unroll
        for (int j = 0; j < 16; j++) {
            int e = j * 256 + tid;
            int kr = e >> 7, px = e & 127;
            float v = xp[j];
            __nv_bfloat16 hi = __float2bfloat16(v);
            Xh[kr * 136 + px] = hi;
            Xl[kr * 136 + px] = __float2bfloat16(v - __bfloat162float(hi));
        }
        __syncthreads();

        // prefetch next chunk into regs (overlaps with MMAs below)
        float xn[16];
        if (cg < 7) {
#pragma unroll
            for (int j = 0; j < 16; j++) {
                int e = j * 256 + tid;
                xn[j] = Xb[(size_t)((cg + 1) * 32 + (e >> 7)) * 6400 + (e & 127)];
            }
        }

        const uint32_t kco = (uint32_t)(cg * 64);
#pragma unroll
        for (int kstep = 0; kstep < 2; kstep++) {
            const uint32_t ko = kco + (uint32_t)(kstep * 32);
            uint32_t Ah[2][4], Al[2][4];
            ldsm_x4(Ah[0][0], Ah[0][1], Ah[0][2], Ah[0][3], aw_hi + ko);
            ldsm_x4(Ah[1][0], Ah[1][1], Ah[1][2], Ah[1][3], aw_hi + 16 * 528 + ko);
            ldsm_x4(Al[0][0], Al[0][1], Al[0][2], Al[0][3], aw_lo + ko);
            ldsm_x4(Al[1][0], Al[1][1], Al[1][2], Al[1][3], aw_lo + 16 * 528 + ko);
            const uint32_t bk = b_base + (uint32_t)(kstep * 16 * 272);
#pragma unroll
            for (int nb = 0; nb < 4; nb++) {
                uint32_t bh0, bh1, bl0, bl1;
                ldsm_x2t(bh0, bh1, bk + (uint32_t)(nb * 16));
                ldsm_x2t(bl0, bl1, bk + 8704 + (uint32_t)(nb * 16));
#pragma unroll
                for (int mb = 0; mb < 2; mb++) {
                    mma16816(acc[mb][nb], Ah[mb], bh0, bh1);
                    mma16816(acc[mb][nb], Ah[mb], bl0, bl1);
                    mma16816(acc[mb][nb], Al[mb], bh0, bh1);
                }
            }
        }
        __syncthreads();
#pragma unroll
        for (int j = 0; j < 16; j++) xp[j] = xn[j];
    }

    // epilogue: BN + SiLU + bf16 split -> Dt[px][ch] (reuses weight smem)
    __nv_bfloat16* Dh = (__nv_bfloat16*)(sm1 + K1_DT);
    __nv_bfloat16* Dl = Dh + 9216;    // +18432B
#pragma unroll
    for (int mb = 0; mb < 2; mb++) {
#pragma unroll
        for (int nb = 0; nb < 4; nb++) {
            int m = warpm * 32 + mb * 16 + (lan >> 2);
            int p = warpn * 32 + nb * 8 + 2 * (lan & 3);
#pragma unroll
            for (int j = 0; j < 4; j++) {
                int mch = m + (j >> 1) * 8;
                int pp  = p + (j & 1);
                float v = acc[mb][nb][j] * scs[mch] + bis[mch];
                float sv = v / (1.f + __expf(-v));
                __nv_bfloat16 hi = __float2bfloat16(sv);
                Dh[pp * 72 + mch] = hi;
                Dl[pp * 72 + mch] = __float2bfloat16(sv - __bfloat162float(hi));
            }
        }
    }
    __syncthreads();

    // coalesced 16B writes to g_midT
    for (int i = tid; i < 2048; i += 256) {
        int split = i >> 10, r = (i >> 3) & 127, ch8 = i & 7;
        uint4 v = *(const uint4*)(sm1 + K1_DT + split * 18432 + r * 144 + ch8 * 16);
        uint4* dst = (uint4*)(split ? g_midT_lo : g_midT_hi);
        dst[(size_t)(b * 6400 + px0 + r) * 8 + ch8] = v;
    }
}

// ---------------------------------------------------------------------------
// K2: 3x3 conv (64->100) via mma.sync bf16 split-3 + BN + shuffle + softmax
// ---------------------------------------------------------------------------
#define SM_ACT_HI 0
#define SM_ACT_LO 25920
#define SM_W      51840
#define SM_SCS    84096
#define SM_BIS    84496
#define SM_TOTAL  84992
#define DT_STRIDE 122

__global__ __launch_bounds__(256, 2)
void k2_enc(const float* __restrict__ g2, const float* __restrict__ b2,
            const float* __restrict__ m2, const float* __restrict__ v2)
{
    extern __shared__ __align__(16) char sm[];
    const int b  = blockIdx.z;
    const int h0 = blockIdx.y * 16;
    const int w0 = blockIdx.x * 8;
    const int tid = threadIdx.x;
    const int wid = tid >> 5;
    const int lan = tid & 31;
    const uint32_t smb = smem_u32(sm);

    if (tid < 100) {
        float is = g2[tid] * rsqrtf(v2[tid] + EPS);
        ((float*)(sm + SM_SCS))[tid] = is;
        ((float*)(sm + SM_BIS))[tid] = b2[tid] - m2[tid] * is;
    }

    for (int k = tid; k < 2880; k += 256) {
        int bufi = (k >= 1440);
        int r = bufi ? k - 1440 : k;
        int row = r >> 3, ch = r & 7;
        int y = row / 10, x = row - y * 10;
        int gh = h0 + y - 1, gw = w0 + x - 1;
        uint4 v = make_uint4(0, 0, 0, 0);
        if (gh >= 0 && gh < HH && gw >= 0 && gw < WW) {
            const uint4* src = (const uint4*)(bufi ? g_midT_lo : g_midT_hi);
            v = src[(size_t)(b * 6400 + gh * WW + gw) * 8 + ch];
        }
        *(uint4*)(sm + (bufi ? SM_ACT_LO : SM_ACT_HI) + row * 144 + (ch << 4)) = v;
    }

    const int warpm = wid & 3;
    const int warpn = wid >> 2;

    float acc[2][7][4];
#pragma unroll
    for (int mb = 0; mb < 2; mb++)
#pragma unroll
        for (int nb = 0; nb < 7; nb++)
#pragma unroll
            for (int j = 0; j < 4; j++) acc[mb][nb][j] = 0.f;

    const int pA0 = warpm * 32 + (lan & 15);
    const int pyA0 = pA0 >> 3, pxA0 = pA0 & 7;
    const uint32_t a_half = (uint32_t)((lan >> 4) << 4);
    const int cB = warpn * 56 + (lan & 7);
    const uint32_t b_half = (uint32_t)(((lan >> 3) & 1) << 4);
    const uint32_t wb_hi = smb + SM_W + (uint32_t)cB * 144 + b_half;
    const uint32_t wb_lo = wb_hi + 16128;

    for (int tap = 0; tap < 9; tap++) {
        const int dy = tap / 3, dx = tap - dy * 3;
        __syncthreads();
        {
            const uint4* gsrc = (const uint4*)g_weP + tap * 2016;
            for (int k = tid; k < 2016; k += 256)
                *(uint4*)(sm + SM_W + (k << 4)) = gsrc[k];
        }
        __syncthreads();

        uint32_t arow0 = (uint32_t)(((pyA0 + dy) * 10 + pxA0 + dx) * 144) + a_half;
        uint32_t arow1 = (uint32_t)(((((pA0 + 16) >> 3) + dy) * 10 + ((pA0 + 16) & 7) + dx) * 144) + a_half;

#pragma unroll
        for (int ks = 0; ks < 4; ks++) {
            const uint32_t ko = (uint32_t)(ks << 5);
            uint32_t Ah[2][4], Al[2][4];
            ldsm_x4(Ah[0][0], Ah[0][1], Ah[0][2], Ah[0][3], smb + SM_ACT_HI + arow0 + ko);
            ldsm_x4(Ah[1][0], Ah[1][1], Ah[1][2], Ah[1][3], smb + SM_ACT_HI + arow1 + ko);
            ldsm_x4(Al[0][0], Al[0][1], Al[0][2], Al[0][3], smb + SM_ACT_LO + arow0 + ko);
            ldsm_x4(Al[1][0], Al[1][1], Al[1][2], Al[1][3], smb + SM_ACT_LO + arow1 + ko);
#pragma unroll
            for (int nb = 0; nb < 7; nb++) {
                uint32_t bh0, bh1, bl0, bl1;
                ldsm_x2(bh0, bh1, wb_hi + (uint32_t)(nb * 1152) + ko);
                ldsm_x2(bl0, bl1, wb_lo + (uint32_t)(nb * 1152) + ko);
#pragma unroll
                for (int mb = 0; mb < 2; mb++) {
                    mma16816(acc[mb][nb], Ah[mb], bh0, bh1);
                    mma16816(acc[mb][nb], Ah[mb], bl0, bl1);
                    mma16816(acc[mb][nb], Al[mb], bh0, bh1);
                }
            }
        }
    }
    __syncthreads();

    float* Dt = (float*)sm;
#pragma unroll
    for (int mb = 0; mb < 2; mb++) {
        int r = warpm * 32 + mb * 16 + (lan >> 2);
#pragma unroll
        for (int nb = 0; nb < 7; nb++) {
            int c = warpn * 56 + nb * 8 + 2 * (lan & 3);
            *(float2*)&Dt[r * DT_STRIDE + c] = make_float2(acc[mb][nb][0], acc[mb][nb][1]);
            *(float2*)&Dt[(r + 8) * DT_STRIDE + c] = make_float2(acc[mb][nb][2], acc[mb][nb][3]);
        }
    }
    __syncthreads();

    const float* scs = (const float*)(sm + SM_SCS);
    const float* bis = (const float*)(sm + SM_BIS);
    for (int it = tid; it < 512; it += 256) {
        int p = it >> 2, q = it & 3;
        float v[25];
        float mx = -1e30f;
#pragma unroll
        for (int k = 0; k < 25; k++) {
            int m = (k << 2) + q;
            float x = Dt[p * DT_STRIDE + m] * scs[m] + bis[m];
            v[k] = x;
            mx = fmaxf(mx, x);
        }
        float s = 0.f;
#pragma unroll
        for (int k = 0; k < 25; k++) {
            float e = __expf(v[k] - mx);
            v[k] = e;
            s += e;
        }
        float inv = 1.f / s;
        int y = 2 * (h0 + (p >> 3)) + (q >> 1);
        int x = 2 * (w0 + (p & 7)) + (q & 1);
#pragma unroll
        for (int k = 0; k < 25; k++)
            g_wm[(((size_t)(b * K2T + k)) * HO + y) * WO + x] = v[k] * inv;
    }
}

// ---------------------------------------------------------------------------
// K3 v4: thread = (pixel, ch-group-of-8), all 4 subpixels per thread.
// X from g_xT via double-buffered cp.async; weights smem-broadcast; f32x2 FMA.
// ---------------------------------------------------------------------------
#define XST 36                   // floats per position row (144B)
#define K3_WS   0                // Ws4[25][64][4] floats = 25600B
#define K3_XS0  25600            // 144*36*4 = 20736B
#define K3_XS1  46336
#define K3_SMEM 67072

__global__ __launch_bounds__(256, 3) void k3_carafe(float* __restrict__ out)
{
    extern __shared__ __align__(16) char sm3[];
    float* Ws4 = (float*)(sm3 + K3_WS);

    const int b = blockIdx.y;
    const int h0 = (blockIdx.x / 10) * 8;
    const int w0 = (blockIdx.x % 10) * 8;
    const int tid = threadIdx.x;

    // CARAFE weights for this tile -> Ws4[t][px][s]
    for (int i = tid; i < 3200; i += 256) {
        int kk = i >> 7, r = i & 127, si = r >> 6, p = r & 63;
        int hh = p >> 3, ww = p & 7;
        int y = 2 * (h0 + hh) + si, x = 2 * (w0 + ww);
        float2 v = *(const float2*)&g_wm[(((size_t)(b * K2T + kk)) * HO + y) * WO + x];
        Ws4[(kk * 64 + p) * 4 + si * 2 + 0] = v.x;
        Ws4[(kk * 64 + p) * 4 + si * 2 + 1] = v.y;
    }

    const float* Xb = g_xT + (size_t)b * 6400 * 256;

#define K3_STAGE(cgx, bufoff) do {                                               \
        for (int i = tid; i < 1152; i += 256) {                                  \
            int pos = i >> 3, c16 = i & 7;                                       \
            int dy = pos / 12, dx = pos - dy * 12;                               \
            int gh = h0 + dy - 2, gw = w0 + dx - 2;                              \
            bool ok = (gh >= 0 && gh < HH && gw >= 0 && gw < WW);                \
            const float* src = Xb + (size_t)(ok ? (gh * WW + gw) : 0) * 256      \
                               + (cgx) * 32 + c16 * 4;                           \
            cp_async16(smem_u32(sm3 + (bufoff)) + (uint32_t)((pos * XST + c16 * 4) * 4), \
                       src, ok ? 16u : 0u);                                      \
        }                                                                        \
        asm volatile("cp.async.commit_group;" ::: "memory");                     \
    } while (0)

    K3_STAGE(0, K3_XS0);
    K3_STAGE(1, K3_XS1);

    const int px = tid >> 2, cg4 = tid & 3;
    const int h = px >> 3, w = px & 7;
    const uint32_t xoff = (uint32_t)(((h * 12 + w) * XST + cg4 * 8) * 4);
    const uint32_t wbase = smem_u32(sm3) + (uint32_t)(px * 16);
    const int y0 = 2 * (h0 + h), x0 = 2 * (w0 + w);

    for (int cg = 0; cg < 8; cg++) {
        if (cg < 7) asm volatile("cp.async.wait_group 1;" ::: "memory");
        else        asm volatile("cp.async.wait_group 0;" ::: "memory");
        __syncthreads();

        const uint32_t xb = smem_u32(sm3) + (uint32_t)((cg & 1) ? K3_XS1 : K3_XS0) + xoff;
        uint64_t acc[4][4];
#pragma unroll
        for (int s = 0; s < 4; s++)
#pragma unroll
            for (int k = 0; k < 4; k++) acc[s][k] = 0ull;

#pragma unroll
        for (int t = 0; t < 25; t++) {
            const int ki = t / 5, kj = t - ki * 5;
            const uint32_t off = (uint32_t)((ki * 12 + kj) * XST * 4);
            float4 wv;
            asm volatile("ld.shared.v4.f32 {%0,%1,%2,%3}, [%4];"
                         : "=f"(wv.x), "=f"(wv.y), "=f"(wv.z), "=f"(wv.w)
                         : "r"(wbase + (uint32_t)(t * 1024)));
            uint64_t w20 = bcast2(wv.x), w21 = bcast2(wv.y);
            uint64_t w22 = bcast2(wv.z), w23 = bcast2(wv.w);
            uint64_t xq0, xq1, xq2, xq3;
            lds_v2u64(xq0, xq1, xb + off);
            lds_v2u64(xq2, xq3, xb + off + 16);
            fma2(acc[0][0], xq0, w20); fma2(acc[0][1], xq1, w20);
            fma2(acc[0][2], xq2, w20); fma2(acc[0][3], xq3, w20);
            fma2(acc[1][0], xq0, w21); fma2(acc[1][1], xq1, w21);
            fma2(acc[1][2], xq2, w21); fma2(acc[1][3], xq3, w21);
            fma2(acc[2][0], xq0, w22); fma2(acc[2][1], xq1, w22);
            fma2(acc[2][2], xq2, w22); fma2(acc[2][3], xq3, w22);
            fma2(acc[3][0], xq0, w23); fma2(acc[3][1], xq1, w23);
            fma2(acc[3][2], xq2, w23); fma2(acc[3][3], xq3, w23);
        }
        __syncthreads();   // all reads of this buffer done before restaging

        float* ob = out + (((size_t)(b * CIN + cg * 32 + cg4 * 8)) * HO + y0) * WO + x0;
#pragma unroll
        for (int k = 0; k < 4; k++) {
            float s0a, s0b, s1a, s1b, s2a, s2b, s3a, s3b;
            unpack2(s0a, s0b, acc[0][k]);
            unpack2(s1a, s1b, acc[1][k]);
            unpack2(s2a, s2b, acc[2][k]);
            unpack2(s3a, s3b, acc[3][k]);
            float* p0 = ob + (size_t)(2 * k) * (HO * WO);
            float* p1 = p0 + HO * WO;
            *(float2*)p0        = make_float2(s0a, s1a);
            *(float2*)(p0 + WO) = make_float2(s2a, s3a);
            *(float2*)p1        = make_float2(s0b, s1b);
            *(float2*)(p1 + WO) = make_float2(s2b, s3b);
        }

        if (cg + 2 < 8) {
            if ((cg & 1) == 0) K3_STAGE(cg + 2, K3_XS0);
            else               K3_STAGE(cg + 2, K3_XS1);
        }
    }
}

// ---------------------------------------------------------------------------
extern "C" void kernel_launch(void* const* d_in, const int* in_sizes, int n_in,
                              void* d_out, int out_size)
{
    const float* X  = (const float*)d_in[0];
    const float* Wc = (const float*)d_in[1];
    const float* g1 = (const float*)d_in[2];
    const float* b1 = (const float*)d_in[3];
    const float* m1 = (const float*)d_in[4];
    const float* v1 = (const float*)d_in[5];
    const float* We = (const float*)d_in[6];
    const float* g2 = (const float*)d_in[7];
    const float* b2 = (const float*)d_in[8];
    const float* m2 = (const float*)d_in[9];
    const float* v2 = (const float*)d_in[10];
    float* out = (float*)d_out;

    cudaFuncSetAttribute(k1_comp, cudaFuncAttributeMaxDynamicSharedMemorySize, K1_SMEM);
    cudaFuncSetAttribute(k2_enc, cudaFuncAttributeMaxDynamicSharedMemorySize, SM_TOTAL);
    cudaFuncSetAttribute(k3_carafe, cudaFuncAttributeMaxDynamicSharedMemorySize, K3_SMEM);

    k0_wprep<<<568, 256>>>(We);
    k0x_transpose<<<dim3(200, 8, BATCH), 256>>>(X);
    k1_comp<<<dim3(50, BATCH), 256, K1_SMEM>>>(X, Wc, g1, b1, m1, v1);
    k2_enc<<<dim3(10, 5, BATCH), 256, SM_TOTAL>>>(g2, b2, m2, v2);
    k3_carafe<<<dim3(100, BATCH), 256, K3_SMEM>>>(out);
}

// round 8
// speedup vs baseline: 1.4931x; 1.0256x over previous
#include <cuda_runtime.h>
#include <cuda_bf16.h>
#include <cstdint>

#define BATCH 16
#define CIN   256
#define HH    80
#define WW    80
#define CMID  64
#define K2T   25
#define HO    160
#define WO    160
#define EPS   1e-5f

// ---------------------------------------------------------------------------
// Device scratch (allocation-free)
// ---------------------------------------------------------------------------
__device__ __align__(16) __nv_bfloat16 g_midT_hi[(size_t)BATCH * 6400 * 64]; // [b][pix][c]
__device__ __align__(16) __nv_bfloat16 g_midT_lo[(size_t)BATCH * 6400 * 64];
// per-tap weights, n-major: [tap][split][c(104)][ic(72)] bf16
__device__ __align__(16) __nv_bfloat16 g_weP[9 * 2 * 104 * 72];
__device__ __align__(16) float g_wm[(size_t)BATCH * K2T * HO * WO];
__device__ __align__(16) float g_xT[(size_t)BATCH * 6400 * 256];   // X pixel-major, 105MB

__device__ __forceinline__ uint32_t smem_u32(const void* p) {
    uint32_t a;
    asm("{ .reg .u64 t; cvta.to.shared.u64 t, %1; cvt.u32.u64 %0, t; }" : "=r"(a) : "l"(p));
    return a;
}
__device__ __forceinline__ void ldsm_x4(uint32_t& r0, uint32_t& r1, uint32_t& r2, uint32_t& r3,
                                        uint32_t addr) {
    asm volatile("ldmatrix.sync.aligned.m8n8.x4.shared.b16 {%0,%1,%2,%3}, [%4];"
                 : "=r"(r0), "=r"(r1), "=r"(r2), "=r"(r3) : "r"(addr));
}
__device__ __forceinline__ void ldsm_x2(uint32_t& r0, uint32_t& r1, uint32_t addr) {
    asm volatile("ldmatrix.sync.aligned.m8n8.x2.shared.b16 {%0,%1}, [%2];"
                 : "=r"(r0), "=r"(r1) : "r"(addr));
}
__device__ __forceinline__ void ldsm_x2t(uint32_t& r0, uint32_t& r1, uint32_t addr) {
    asm volatile("ldmatrix.sync.aligned.m8n8.x2.trans.shared.b16 {%0,%1}, [%2];"
                 : "=r"(r0), "=r"(r1) : "r"(addr));
}
__device__ __forceinline__ void mma16816(float* d, const uint32_t* a, uint32_t b0, uint32_t b1) {
    asm volatile(
        "mma.sync.aligned.m16n8k16.row.col.f32.bf16.bf16.f32 "
        "{%0,%1,%2,%3}, {%4,%5,%6,%7}, {%8,%9}, {%0,%1,%2,%3};"
        : "+f"(d[0]), "+f"(d[1]), "+f"(d[2]), "+f"(d[3])
        : "r"(a[0]), "r"(a[1]), "r"(a[2]), "r"(a[3]), "r"(b0), "r"(b1));
}
// Packed fp32 helpers (Blackwell f32x2 pipe)
__device__ __forceinline__ void fma2(uint64_t& d, uint64_t a, uint64_t b) {
    asm("fma.rn.f32x2 %0, %1, %2, %0;" : "+l"(d) : "l"(a), "l"(b));
}
__device__ __forceinline__ uint64_t bcast2(float x) {
    uint64_t r;
    asm("mov.b64 %0, {%1, %1};" : "=l"(r) : "f"(x));
    return r;
}
__device__ __forceinline__ void unpack2(float& lo, float& hi, uint64_t v) {
    asm("mov.b64 {%0, %1}, %2;" : "=f"(lo), "=f"(hi) : "l"(v));
}
__device__ __forceinline__ void lds_v2u64(uint64_t& a, uint64_t& b, uint32_t addr) {
    asm volatile("ld.shared.v2.u64 {%0, %1}, [%2];" : "=l"(a), "=l"(b) : "r"(addr));
}
__device__ __forceinline__ void cp_async16(uint32_t saddr, const void* gptr, uint32_t sz) {
    asm volatile("cp.async.cg.shared.global [%0], [%1], 16, %2;"
                 :: "r"(saddr), "l"(gptr), "r"(sz) : "memory");
}

// ---------------------------------------------------------------------------
// K0: conv2 weights -> [tap][split][c pad 104][ic pad 72] bf16 split
// ---------------------------------------------------------------------------
__global__ __launch_bounds__(256) void k0_wprep(const float* __restrict__ We) {
    int i = blockIdx.x * 256 + threadIdx.x;
    if (i >= 9 * 2 * 104 * 72) return;
    int tap = i / 14976, r = i % 14976;
    int s = r / 7488; r %= 7488;
    int c = r / 72, ic = r % 72;
    float v = (c < 100 && ic < 64) ? We[c * 576 + ic * 9 + tap] : 0.f;
    __nv_bfloat16 hi = __float2bfloat16(v);
    g_weP[i] = s ? __float2bfloat16(v - __bfloat162float(hi)) : hi;
}

// ---------------------------------------------------------------------------
// K0x: transpose X (b, c, p) -> g_xT (b, p, c). 32x32 tiles via smem.
// ---------------------------------------------------------------------------
__global__ __launch_bounds__(256) void k0x_transpose(const float* __restrict__ X) {
    __shared__ float t[32][33];
    const int b = blockIdx.z;
    const int p0 = blockIdx.x * 32, c0 = blockIdx.y * 32;
    const int tx = threadIdx.x & 31, ty = threadIdx.x >> 5;
    const float* src = X + ((size_t)b * 256 + c0) * 6400 + p0;
#pragma unroll
    for (int r = 0; r < 4; r++)
        t[ty + 8 * r][tx] = src[(size_t)(ty + 8 * r) * 6400 + tx];
    __syncthreads();
    float* dst = g_xT + ((size_t)b * 6400 + p0) * 256 + c0;
#pragma unroll
    for (int r = 0; r < 4; r++)
        dst[(size_t)(ty + 8 * r) * 256 + tx] = t[tx][ty + 8 * r];
}

// ---------------------------------------------------------------------------
// K1 v2: 1x1 conv (256->64) via mma.sync bf16 split-3 + BN + SiLU.
// ---------------------------------------------------------------------------
#define K1_SW    0            // weights hi [64][528B] = 33792; lo at +33792
#define K1_SXS   67584        // X chunk [split][32k][272B] = 8704*2
#define K1_SBN   84992        // scs 256B + bis 256B
#define K1_SMEM  85504
#define K1_DT    0            // epilogue [split][128px][144B], reuses weights

__global__ __launch_bounds__(256, 2) void k1_comp(
    const float* __restrict__ X, const float* __restrict__ Wc,
    const float* __restrict__ g1, const float* __restrict__ b1,
    const float* __restrict__ m1, const float* __restrict__ v1)
{
    extern __shared__ __align__(16) char sm1[];
    const int b   = blockIdx.y;
    const int px0 = blockIdx.x * 128;
    const int tid = threadIdx.x;
    const int wid = tid >> 5, lan = tid & 31;
    const uint32_t smb = smem_u32(sm1);

    __nv_bfloat16* Wh = (__nv_bfloat16*)(sm1 + K1_SW);
    __nv_bfloat16* Wl = Wh + 16896;
    for (int i = tid; i < 16384; i += 256) {
        int m = i >> 8, k = i & 255;
        float v = Wc[i];
        __nv_bfloat16 hi = __float2bfloat16(v);
        Wh[m * 264 + k] = hi;
        Wl[m * 264 + k] = __float2bfloat16(v - __bfloat162float(hi));
    }
    float* scs = (float*)(sm1 + K1_SBN);
    float* bis = scs + 64;
    if (tid < 64) {
        float is = g1[tid] * rsqrtf(v1[tid] + EPS);
        scs[tid] = is;
        bis[tid] = b1[tid] - m1[tid] * is;
    }

    const float* Xb = X + (size_t)b * 256 * 6400 + px0;
    __nv_bfloat16* Xh = (__nv_bfloat16*)(sm1 + K1_SXS);
    __nv_bfloat16* Xl = Xh + 4352;

    float xp[16];
#pragma unroll
    for (int j = 0; j < 16; j++) {
        int e = j * 256 + tid;
        xp[j] = Xb[(size_t)(e >> 7) * 6400 + (e & 127)];
    }

    const int warpm = wid & 1;
    const int warpn = wid >> 1;

    float acc[2][4][4];
#pragma unroll
    for (int mb = 0; mb < 2; mb++)
#pragma unroll
        for (int nb = 0; nb < 4; nb++)
#pragma unroll
            for (int j = 0; j < 4; j++) acc[mb][nb][j] = 0.f;

    const uint32_t a_row = (uint32_t)(warpm * 32 + (lan & 15));
    const uint32_t a_half = (uint32_t)((lan >> 4) << 4);
    const uint32_t aw_hi = smb + K1_SW + a_row * 528 + a_half;
    const uint32_t aw_lo = aw_hi + 33792;
    const uint32_t b_base = smb + K1_SXS + (uint32_t)((lan & 15) * 272 + warpn * 64);

#pragma unroll 1
    for (int cg = 0; cg < 8; cg++) {
#pragma unroll
        for (int j = 0; j < 16; j++) {
            int e = j * 256 + tid;
            int kr = e >> 7, px = e & 127;
            float v = xp[j];
            __nv_bfloat16 hi = __float2bfloat16(v);
            Xh[kr * 136 + px] = hi;
            Xl[kr * 136 + px] = __float2bfloat16(v - __bfloat162float(hi));
        }
        __syncthreads();

        float xn[16];
        if (cg < 7) {
#pragma unroll
            for (int j = 0; j < 16; j++) {
                int e = j * 256 + tid;
                xn[j] = Xb[(size_t)((cg + 1) * 32 + (e >> 7)) * 6400 + (e & 127)];
            }
        }

        const uint32_t kco = (uint32_t)(cg * 64);
#pragma unroll
        for (int kstep = 0; kstep < 2; kstep++) {
            const uint32_t ko = kco + (uint32_t)(kstep * 32);
            uint32_t Ah[2][4], Al[2][4];
            ldsm_x4(Ah[0][0], Ah[0][1], Ah[0][2], Ah[0][3], aw_hi + ko);
            ldsm_x4(Ah[1][0], Ah[1][1], Ah[1][2], Ah[1][3], aw_hi + 16 * 528 + ko);
            ldsm_x4(Al[0][0], Al[0][1], Al[0][2], Al[0][3], aw_lo + ko);
            ldsm_x4(Al[1][0], Al[1][1], Al[1][2], Al[1][3], aw_lo + 16 * 528 + ko);
            const uint32_t bk = b_base + (uint32_t)(kstep * 16 * 272);
#pragma unroll
            for (int nb = 0; nb < 4; nb++) {
                uint32_t bh0, bh1, bl0, bl1;
                ldsm_x2t(bh0, bh1, bk + (uint32_t)(nb * 16));
                ldsm_x2t(bl0, bl1, bk + 8704 + (uint32_t)(nb * 16));
#pragma unroll
                for (int mb = 0; mb < 2; mb++) {
                    mma16816(acc[mb][nb], Ah[mb], bh0, bh1);
                    mma16816(acc[mb][nb], Ah[mb], bl0, bl1);
                    mma16816(acc[mb][nb], Al[mb], bh0, bh1);
                }
            }
        }
        __syncthreads();
#pragma unroll
        for (int j = 0; j < 16; j++) xp[j] = xn[j];
    }

    __nv_bfloat16* Dh = (__nv_bfloat16*)(sm1 + K1_DT);
    __nv_bfloat16* Dl = Dh + 9216;
#pragma unroll
    for (int mb = 0; mb < 2; mb++) {
#pragma unroll
        for (int nb = 0; nb < 4; nb++) {
            int m = warpm * 32 + mb * 16 + (lan >> 2);
            int p = warpn * 32 + nb * 8 + 2 * (lan & 3);
#pragma unroll
            for (int j = 0; j < 4; j++) {
                int mch = m + (j >> 1) * 8;
                int pp  = p + (j & 1);
                float v = acc[mb][nb][j] * scs[mch] + bis[mch];
                float sv = v / (1.f + __expf(-v));
                __nv_bfloat16 hi = __float2bfloat16(sv);
                Dh[pp * 72 + mch] = hi;
                Dl[pp * 72 + mch] = __float2bfloat16(sv - __bfloat162float(hi));
            }
        }
    }
    __syncthreads();

    for (int i = tid; i < 2048; i += 256) {
        int split = i >> 10, r = (i >> 3) & 127, ch8 = i & 7;
        uint4 v = *(const uint4*)(sm1 + K1_DT + split * 18432 + r * 144 + ch8 * 16);
        uint4* dst = (uint4*)(split ? g_midT_lo : g_midT_hi);
        dst[(size_t)(b * 6400 + px0 + r) * 8 + ch8] = v;
    }
}

// ---------------------------------------------------------------------------
// K2 v2: 3x3 conv via mma.sync bf16 split-3, cp.async double-buffered weights.
// N pad = 104 (guard region absorbs ldsm overreach to ch 111).
// ---------------------------------------------------------------------------
#define SM_ACT_HI 0
#define SM_ACT_LO 25920
#define SM_WB0    51840       // 29952B each ([split 14976][104][144B])
#define SM_WB1    81792
// guard: 111744..113472 (1728B) absorbs nb6 overreach of WB1
#define SM_SCS    113472
#define SM_BIS    113872
#define SM_TOTAL  114272
#define WSPLIT    14976
#define DT_STRIDE 122

__global__ __launch_bounds__(256, 2)
void k2_enc(const float* __restrict__ g2, const float* __restrict__ b2,
            const float* __restrict__ m2, const float* __restrict__ v2)
{
    extern __shared__ __align__(16) char sm[];
    const int b  = blockIdx.z;
    const int h0 = blockIdx.y * 16;
    const int w0 = blockIdx.x * 8;
    const int tid = threadIdx.x;
    const int wid = tid >> 5;
    const int lan = tid & 31;
    const uint32_t smb = smem_u32(sm);

    if (tid < 100) {
        float is = g2[tid] * rsqrtf(v2[tid] + EPS);
        ((float*)(sm + SM_SCS))[tid] = is;
        ((float*)(sm + SM_BIS))[tid] = b2[tid] - m2[tid] * is;
    }

    // stage 18x10 activation tile (hi+lo)
    for (int k = tid; k < 2880; k += 256) {
        int bufi = (k >= 1440);
        int r = bufi ? k - 1440 : k;
        int row = r >> 3, ch = r & 7;
        int y = row / 10, x = row - y * 10;
        int gh = h0 + y - 1, gw = w0 + x - 1;
        uint4 v = make_uint4(0, 0, 0, 0);
        if (gh >= 0 && gh < HH && gw >= 0 && gw < WW) {
            const uint4* src = (const uint4*)(bufi ? g_midT_lo : g_midT_hi);
            v = src[(size_t)(b * 6400 + gh * WW + gw) * 8 + ch];
        }
        *(uint4*)(sm + (bufi ? SM_ACT_LO : SM_ACT_HI) + row * 144 + (ch << 4)) = v;
    }

#define K2_WSTAGE(tapx, bufoff) do {                                          \
        const uint4* gsrc = (const uint4*)g_weP + (tapx) * 1872;              \
        for (int k = tid; k < 1872; k += 256)                                 \
            cp_async16(smb + (bufoff) + (uint32_t)(k << 4), gsrc + k, 16);    \
        asm volatile("cp.async.commit_group;" ::: "memory");                  \
    } while (0)

    K2_WSTAGE(0, SM_WB0);
    K2_WSTAGE(1, SM_WB1);

    const int warpm = wid & 3;
    const int warpn = wid >> 2;

    float acc[2][7][4];
#pragma unroll
    for (int mb = 0; mb < 2; mb++)
#pragma unroll
        for (int nb = 0; nb < 7; nb++)
#pragma unroll
            for (int j = 0; j < 4; j++) acc[mb][nb][j] = 0.f;

    const int pA0 = warpm * 32 + (lan & 15);
    const int pyA0 = pA0 >> 3, pxA0 = pA0 & 7;
    const uint32_t a_half = (uint32_t)((lan >> 4) << 4);
    const int cB = warpn * 56 + (lan & 7);
    const uint32_t b_half = (uint32_t)(((lan >> 3) & 1) << 4);
    const uint32_t wb_off = (uint32_t)cB * 144 + b_half;

    for (int tap = 0; tap < 9; tap++) {
        const int dy = tap / 3, dx = tap - dy * 3;
        if (tap < 8) asm volatile("cp.async.wait_group 1;" ::: "memory");
        else         asm volatile("cp.async.wait_group 0;" ::: "memory");
        __syncthreads();

        const uint32_t wbuf = smb + ((tap & 1) ? SM_WB1 : SM_WB0);
        const uint32_t wb_hi = wbuf + wb_off;
        const uint32_t wb_lo = wb_hi + WSPLIT;

        uint32_t arow0 = (uint32_t)(((pyA0 + dy) * 10 + pxA0 + dx) * 144) + a_half;
        uint32_t arow1 = (uint32_t)(((((pA0 + 16) >> 3) + dy) * 10 + ((pA0 + 16) & 7) + dx) * 144) + a_half;

#pragma unroll
        for (int ks = 0; ks < 4; ks++) {
            const uint32_t ko = (uint32_t)(ks << 5);
            uint32_t Ah[2][4], Al[2][4];
            ldsm_x4(Ah[0][0], Ah[0][1], Ah[0][2], Ah[0][3], smb + SM_ACT_HI + arow0 + ko);
            ldsm_x4(Ah[1][0], Ah[1][1], Ah[1][2], Ah[1][3], smb + SM_ACT_HI + arow1 + ko);
            ldsm_x4(Al[0][0], Al[0][1], Al[0][2], Al[0][3], smb + SM_ACT_LO + arow0 + ko);
            ldsm_x4(Al[1][0], Al[1][1], Al[1][2], Al[1][3], smb + SM_ACT_LO + arow1 + ko);
#pragma unroll
            for (int nb = 0; nb < 7; nb++) {
                uint32_t bh0, bh1, bl0, bl1;
                ldsm_x2(bh0, bh1, wb_hi + (uint32_t)(nb * 1152) + ko);
                ldsm_x2(bl0, bl1, wb_lo + (uint32_t)(nb * 1152) + ko);
#pragma unroll
                for (int mb = 0; mb < 2; mb++) {
                    mma16816(acc[mb][nb], Ah[mb], bh0, bh1);
                    mma16816(acc[mb][nb], Ah[mb], bl0, bl1);
                    mma16816(acc[mb][nb], Al[mb], bh0, bh1);
                }
            }
        }
        __syncthreads();   // ldsm of this buffer done before restaging
        if (tap + 2 < 9) {
            if ((tap & 1) == 0) K2_WSTAGE(tap + 2, SM_WB0);
            else                K2_WSTAGE(tap + 2, SM_WB1);
        }
    }

    float* Dt = (float*)sm;
#pragma unroll
    for (int mb = 0; mb < 2; mb++) {
        int r = warpm * 32 + mb * 16 + (lan >> 2);
#pragma unroll
        for (int nb = 0; nb < 7; nb++) {
            int c = warpn * 56 + nb * 8 + 2 * (lan & 3);
            *(float2*)&Dt[r * DT_STRIDE + c] = make_float2(acc[mb][nb][0], acc[mb][nb][1]);
            *(float2*)&Dt[(r + 8) * DT_STRIDE + c] = make_float2(acc[mb][nb][2], acc[mb][nb][3]);
        }
    }
    __syncthreads();

    const float* scs = (const float*)(sm + SM_SCS);
    const float* bis = (const float*)(sm + SM_BIS);
    for (int it = tid; it < 512; it += 256) {
        int p = it >> 2, q = it & 3;
        float v[25];
        float mx = -1e30f;
#pragma unroll
        for (int k = 0; k < 25; k++) {
            int m = (k << 2) + q;
            float x = Dt[p * DT_STRIDE + m] * scs[m] + bis[m];
            v[k] = x;
            mx = fmaxf(mx, x);
        }
        float s = 0.f;
#pragma unroll
        for (int k = 0; k < 25; k++) {
            float e = __expf(v[k] - mx);
            v[k] = e;
            s += e;
        }
        float inv = 1.f / s;
        int y = 2 * (h0 + (p >> 3)) + (q >> 1);
        int x = 2 * (w0 + (p & 7)) + (q & 1);
#pragma unroll
        for (int k = 0; k < 25; k++)
            g_wm[(((size_t)(b * K2T + k)) * HO + y) * WO + x] = v[k] * inv;
    }
}

// ---------------------------------------------------------------------------
// K3 v4: thread = (pixel, ch-group-of-8), all 4 subpixels per thread.
// ---------------------------------------------------------------------------
#define XST 36
#define K3_WS   0
#define K3_XS0  25600
#define K3_XS1  46336
#define K3_SMEM 67072

__global__ __launch_bounds__(256, 3) void k3_carafe(float* __restrict__ out)
{
    extern __shared__ __align__(16) char sm3[];
    float* Ws4 = (float*)(sm3 + K3_WS);

    const int b = blockIdx.y;
    const int h0 = (blockIdx.x / 10) * 8;
    const int w0 = (blockIdx.x % 10) * 8;
    const int tid = threadIdx.x;

    for (int i = tid; i < 3200; i += 256) {
        int kk = i >> 7, r = i & 127, si = r >> 6, p = r & 63;
        int hh = p >> 3, ww = p & 7;
        int y = 2 * (h0 + hh) + si, x = 2 * (w0 + ww);
        float2 v = *(const float2*)&g_wm[(((size_t)(b * K2T + kk)) * HO + y) * WO + x];
        Ws4[(kk * 64 + p) * 4 + si * 2 + 0] = v.x;
        Ws4[(kk * 64 + p) * 4 + si * 2 + 1] = v.y;
    }

    const float* Xb = g_xT + (size_t)b * 6400 * 256;

#define K3_STAGE(cgx, bufoff) do {                                               \
        for (int i = tid; i < 1152; i += 256) {                                  \
            int pos = i >> 3, c16 = i & 7;                                       \
            int dy = pos / 12, dx = pos - dy * 12;                               \
            int gh = h0 + dy - 2, gw = w0 + dx - 2;                              \
            bool ok = (gh >= 0 && gh < HH && gw >= 0 && gw < WW);                \
            const float* src = Xb + (size_t)(ok ? (gh * WW + gw) : 0) * 256      \
                               + (cgx) * 32 + c16 * 4;                           \
            cp_async16(smem_u32(sm3 + (bufoff)) + (uint32_t)((pos * XST + c16 * 4) * 4), \
                       src, ok ? 16u : 0u);                                      \
        }                                                                        \
        asm volatile("cp.async.commit_group;" ::: "memory");                     \
    } while (0)

    K3_STAGE(0, K3_XS0);
    K3_STAGE(1, K3_XS1);

    const int px = tid >> 2, cg4 = tid & 3;
    const int h = px >> 3, w = px & 7;
    const uint32_t xoff = (uint32_t)(((h * 12 + w) * XST + cg4 * 8) * 4);
    const uint32_t wbase = smem_u32(sm3) + (uint32_t)(px * 16);
    const int y0 = 2 * (h0 + h), x0 = 2 * (w0 + w);

    for (int cg = 0; cg < 8; cg++) {
        if (cg < 7) asm volatile("cp.async.wait_group 1;" ::: "memory");
        else        asm volatile("cp.async.wait_group 0;" ::: "memory");
        __syncthreads();

        const uint32_t xb = smem_u32(sm3) + (uint32_t)((cg & 1) ? K3_XS1 : K3_XS0) + xoff;
        uint64_t acc[4][4];
#pragma unroll
        for (int s = 0; s < 4; s++)
#pragma unroll
            for (int k = 0; k < 4; k++) acc[s][k] = 0ull;

#pragma unroll
        for (int t = 0; t < 25; t++) {
            const int ki = t / 5, kj = t - ki * 5;
            const uint32_t off = (uint32_t)((ki * 12 + kj) * XST * 4);
            float4 wv;
            asm volatile("ld.shared.v4.f32 {%0,%1,%2,%3}, [%4];"
                         : "=f"(wv.x), "=f"(wv.y), "=f"(wv.z), "=f"(wv.w)
                         : "r"(wbase + (uint32_t)(t * 1024)));
            uint64_t w20 = bcast2(wv.x), w21 = bcast2(wv.y);
            uint64_t w22 = bcast2(wv.z), w23 = bcast2(wv.w);
            uint64_t xq0, xq1, xq2, xq3;
            lds_v2u64(xq0, xq1, xb + off);
            lds_v2u64(xq2, xq3, xb + off + 16);
            fma2(acc[0][0], xq0, w20); fma2(acc[0][1], xq1, w20);
            fma2(acc[0][2], xq2, w20); fma2(acc[0][3], xq3, w20);
            fma2(acc[1][0], xq0, w21); fma2(acc[1][1], xq1, w21);
            fma2(acc[1][2], xq2, w21); fma2(acc[1][3], xq3, w21);
            fma2(acc[2][0], xq0, w22); fma2(acc[2][1], xq1, w22);
            fma2(acc[2][2], xq2, w22); fma2(acc[2][3], xq3, w22);
            fma2(acc[3][0], xq0, w23); fma2(acc[3][1], xq1, w23);
            fma2(acc[3][2], xq2, w23); fma2(acc[3][3], xq3, w23);
        }
        __syncthreads();

        float* ob = out + (((size_t)(b * CIN + cg * 32 + cg4 * 8)) * HO + y0) * WO + x0;
#pragma unroll
        for (int k = 0; k < 4; k++) {
            float s0a, s0b, s1a, s1b, s2a, s2b, s3a, s3b;
            unpack2(s0a, s0b, acc[0][k]);
            unpack2(s1a, s1b, acc[1][k]);
            unpack2(s2a, s2b, acc[2][k]);
            unpack2(s3a, s3b, acc[3][k]);
            float* p0 = ob + (size_t)(2 * k) * (HO * WO);
            float* p1 = p0 + HO * WO;
            *(float2*)p0        = make_float2(s0a, s1a);
            *(float2*)(p0 + WO) = make_float2(s2a, s3a);
            *(float2*)p1        = make_float2(s0b, s1b);
            *(float2*)(p1 + WO) = make_float2(s2b, s3b);
        }

        if (cg + 2 < 8) {
            if ((cg & 1) == 0) K3_STAGE(cg + 2, K3_XS0);
            else               K3_STAGE(cg + 2, K3_XS1);
        }
    }
}

// ---------------------------------------------------------------------------
extern "C" void kernel_launch(void* const* d_in, const int* in_sizes, int n_in,
                              void* d_out, int out_size)
{
    const float* X  = (const float*)d_in[0];
    const float* Wc = (const float*)d_in[1];
    const float* g1 = (const float*)d_in[2];
    const float* b1 = (const float*)d_in[3];
    const float* m1 = (const float*)d_in[4];
    const float* v1 = (const float*)d_in[5];
    const float* We = (const float*)d_in[6];
    const float* g2 = (const float*)d_in[7];
    const float* b2 = (const float*)d_in[8];
    const float* m2 = (const float*)d_in[9];
    const float* v2 = (const float*)d_in[10];
    float* out = (float*)d_out;

    cudaFuncSetAttribute(k1_comp, cudaFuncAttributeMaxDynamicSharedMemorySize, K1_SMEM);
    cudaFuncSetAttribute(k2_enc, cudaFuncAttributeMaxDynamicSharedMemorySize, SM_TOTAL);
    cudaFuncSetAttribute(k3_carafe, cudaFuncAttributeMaxDynamicSharedMemorySize, K3_SMEM);

    k0_wprep<<<527, 256>>>(We);
    k0x_transpose<<<dim3(200, 8, BATCH), 256>>>(X);
    k1_comp<<<dim3(50, BATCH), 256, K1_SMEM>>>(X, Wc, g1, b1, m1, v1);
    k2_enc<<<dim3(10, 5, BATCH), 256, SM_TOTAL>>>(g2, b2, m2, v2);
    k3_carafe<<<dim3(100, BATCH), 256, K3_SMEM>>>(out);
}

// round 9
// speedup vs baseline: 1.5257x; 1.0219x over previous
#include <cuda_runtime.h>
#include <cuda_bf16.h>
#include <cstdint>

#define BATCH 16
#define CIN   256
#define HH    80
#define WW    80
#define CMID  64
#define K2T   25
#define HO    160
#define WO    160
#define EPS   1e-5f

// ---------------------------------------------------------------------------
// Device scratch (allocation-free)
// ---------------------------------------------------------------------------
__device__ __align__(16) __nv_bfloat16 g_midT_hi[(size_t)BATCH * 6400 * 64]; // [b][pix][c]
__device__ __align__(16) __nv_bfloat16 g_midT_lo[(size_t)BATCH * 6400 * 64];
// per-tap weights, n-major: [tap][split][c(104)][ic(72)] bf16
__device__ __align__(16) __nv_bfloat16 g_weP[9 * 2 * 104 * 72];
__device__ __align__(16) float g_wm[(size_t)BATCH * K2T * HO * WO];
__device__ __align__(16) float g_xT[(size_t)BATCH * 6400 * 256];   // X pixel-major, 105MB

__device__ __forceinline__ uint32_t smem_u32(const void* p) {
    uint32_t a;
    asm("{ .reg .u64 t; cvta.to.shared.u64 t, %1; cvt.u32.u64 %0, t; }" : "=r"(a) : "l"(p));
    return a;
}
__device__ __forceinline__ void ldsm_x4(uint32_t& r0, uint32_t& r1, uint32_t& r2, uint32_t& r3,
                                        uint32_t addr) {
    asm volatile("ldmatrix.sync.aligned.m8n8.x4.shared.b16 {%0,%1,%2,%3}, [%4];"
                 : "=r"(r0), "=r"(r1), "=r"(r2), "=r"(r3) : "r"(addr));
}
__device__ __forceinline__ void ldsm_x2(uint32_t& r0, uint32_t& r1, uint32_t addr) {
    asm volatile("ldmatrix.sync.aligned.m8n8.x2.shared.b16 {%0,%1}, [%2];"
                 : "=r"(r0), "=r"(r1) : "r"(addr));
}
__device__ __forceinline__ void ldsm_x2t(uint32_t& r0, uint32_t& r1, uint32_t addr) {
    asm volatile("ldmatrix.sync.aligned.m8n8.x2.trans.shared.b16 {%0,%1}, [%2];"
                 : "=r"(r0), "=r"(r1) : "r"(addr));
}
__device__ __forceinline__ void mma16816(float* d, const uint32_t* a, uint32_t b0, uint32_t b1) {
    asm volatile(
        "mma.sync.aligned.m16n8k16.row.col.f32.bf16.bf16.f32 "
        "{%0,%1,%2,%3}, {%4,%5,%6,%7}, {%8,%9}, {%0,%1,%2,%3};"
        : "+f"(d[0]), "+f"(d[1]), "+f"(d[2]), "+f"(d[3])
        : "r"(a[0]), "r"(a[1]), "r"(a[2]), "r"(a[3]), "r"(b0), "r"(b1));
}
// Packed fp32 helpers (Blackwell f32x2 pipe)
__device__ __forceinline__ void fma2(uint64_t& d, uint64_t a, uint64_t b) {
    asm("fma.rn.f32x2 %0, %1, %2, %0;" : "+l"(d) : "l"(a), "l"(b));
}
__device__ __forceinline__ uint64_t bcast2(float x) {
    uint64_t r;
    asm("mov.b64 %0, {%1, %1};" : "=l"(r) : "f"(x));
    return r;
}
__device__ __forceinline__ void unpack2(float& lo, float& hi, uint64_t v) {
    asm("mov.b64 {%0, %1}, %2;" : "=f"(lo), "=f"(hi) : "l"(v));
}
__device__ __forceinline__ void lds_v2u64(uint64_t& a, uint64_t& b, uint32_t addr) {
    asm volatile("ld.shared.v2.u64 {%0, %1}, [%2];" : "=l"(a), "=l"(b) : "r"(addr));
}
__device__ __forceinline__ void cp_async16(uint32_t saddr, const void* gptr, uint32_t sz) {
    asm volatile("cp.async.cg.shared.global [%0], [%1], 16, %2;"
                 :: "r"(saddr), "l"(gptr), "r"(sz) : "memory");
}

// ---------------------------------------------------------------------------
// K0: conv2 weights -> [tap][split][c pad 104][ic pad 72] bf16 split
// ---------------------------------------------------------------------------
__global__ __launch_bounds__(256) void k0_wprep(const float* __restrict__ We) {
    int i = blockIdx.x * 256 + threadIdx.x;
    if (i >= 9 * 2 * 104 * 72) return;
    int tap = i / 14976, r = i % 14976;
    int s = r / 7488; r %= 7488;
    int c = r / 72, ic = r % 72;
    float v = (c < 100 && ic < 64) ? We[c * 576 + ic * 9 + tap] : 0.f;
    __nv_bfloat16 hi = __float2bfloat16(v);
    g_weP[i] = s ? __float2bfloat16(v - __bfloat162float(hi)) : hi;
}

// ---------------------------------------------------------------------------
// K0x: transpose X (b, c, p) -> g_xT (b, p, c). 32x32 tiles via smem.
// ---------------------------------------------------------------------------
__global__ __launch_bounds__(256) void k0x_transpose(const float* __restrict__ X) {
    __shared__ float t[32][33];
    const int b = blockIdx.z;
    const int p0 = blockIdx.x * 32, c0 = blockIdx.y * 32;
    const int tx = threadIdx.x & 31, ty = threadIdx.x >> 5;
    const float* src = X + ((size_t)b * 256 + c0) * 6400 + p0;
#pragma unroll
    for (int r = 0; r < 4; r++)
        t[ty + 8 * r][tx] = src[(size_t)(ty + 8 * r) * 6400 + tx];
    __syncthreads();
    float* dst = g_xT + ((size_t)b * 6400 + p0) * 256 + c0;
#pragma unroll
    for (int r = 0; r < 4; r++)
        dst[(size_t)(ty + 8 * r) * 256 + tx] = t[tx][ty + 8 * r];
}

// ---------------------------------------------------------------------------
// K1 v2: 1x1 conv (256->64) via mma.sync bf16 split-3 + BN + SiLU.
// ---------------------------------------------------------------------------
#define K1_SW    0            // weights hi [64][528B] = 33792; lo at +33792
#define K1_SXS   67584        // X chunk [split][32k][272B] = 8704*2
#define K1_SBN   84992        // scs 256B + bis 256B
#define K1_SMEM  85504
#define K1_DT    0            // epilogue [split][128px][144B], reuses weights

__global__ __launch_bounds__(256, 2) void k1_comp(
    const float* __restrict__ X, const float* __restrict__ Wc,
    const float* __restrict__ g1, const float* __restrict__ b1,
    const float* __restrict__ m1, const float* __restrict__ v1)
{
    extern __shared__ __align__(16) char sm1[];
    const int b   = blockIdx.y;
    const int px0 = blockIdx.x * 128;
    const int tid = threadIdx.x;
    const int wid = tid >> 5, lan = tid & 31;
    const uint32_t smb = smem_u32(sm1);

    __nv_bfloat16* Wh = (__nv_bfloat16*)(sm1 + K1_SW);
    __nv_bfloat16* Wl = Wh + 16896;
    for (int i = tid; i < 16384; i += 256) {
        int m = i >> 8, k = i & 255;
        float v = Wc[i];
        __nv_bfloat16 hi = __float2bfloat16(v);
        Wh[m * 264 + k] = hi;
        Wl[m * 264 + k] = __float2bfloat16(v - __bfloat162float(hi));
    }
    float* scs = (float*)(sm1 + K1_SBN);
    float* bis = scs + 64;
    if (tid < 64) {
        float is = g1[tid] * rsqrtf(v1[tid] + EPS);
        scs[tid] = is;
        bis[tid] = b1[tid] - m1[tid] * is;
    }

    const float* Xb = X + (size_t)b * 256 * 6400 + px0;
    __nv_bfloat16* Xh = (__nv_bfloat16*)(sm1 + K1_SXS);
    __nv_bfloat16* Xl = Xh + 4352;

    float xp[16];
#pragma unroll
    for (int j = 0; j < 16; j++) {
        int e = j * 256 + tid;
        xp[j] = Xb[(size_t)(e >> 7) * 6400 + (e & 127)];
    }

    const int warpm = wid & 1;
    const int warpn = wid >> 1;

    float acc[2][4][4];
#pragma unroll
    for (int mb = 0; mb < 2; mb++)
#pragma unroll
        for (int nb = 0; nb < 4; nb++)
#pragma unroll
            for (int j = 0; j < 4; j++) acc[mb][nb][j] = 0.f;

    const uint32_t a_row = (uint32_t)(warpm * 32 + (lan & 15));
    const uint32_t a_half = (uint32_t)((lan >> 4) << 4);
    const uint32_t aw_hi = smb + K1_SW + a_row * 528 + a_half;
    const uint32_t aw_lo = aw_hi + 33792;
    const uint32_t b_base = smb + K1_SXS + (uint32_t)((lan & 15) * 272 + warpn * 64);

#pragma unroll 1
    for (int cg = 0; cg < 8; cg++) {
#pragma unroll
        for (int j = 0; j < 16; j++) {
            int e = j * 256 + tid;
            int kr = e >> 7, px = e & 127;
            float v = xp[j];
            __nv_bfloat16 hi = __float2bfloat16(v);
            Xh[kr * 136 + px] = hi;
            Xl[kr * 136 + px] = __float2bfloat16(v - __bfloat162float(hi));
        }
        __syncthreads();

        float xn[16];
        if (cg < 7) {
#pragma unroll
            for (int j = 0; j < 16; j++) {
                int e = j * 256 + tid;
                xn[j] = Xb[(size_t)((cg + 1) * 32 + (e >> 7)) * 6400 + (e & 127)];
            }
        }

        const uint32_t kco = (uint32_t)(cg * 64);
#pragma unroll
        for (int kstep = 0; kstep < 2; kstep++) {
            const uint32_t ko = kco + (uint32_t)(kstep * 32);
            uint32_t Ah[2][4], Al[2][4];
            ldsm_x4(Ah[0][0], Ah[0][1], Ah[0][2], Ah[0][3], aw_hi + ko);
            ldsm_x4(Ah[1][0], Ah[1][1], Ah[1][2], Ah[1][3], aw_hi + 16 * 528 + ko);
            ldsm_x4(Al[0][0], Al[0][1], Al[0][2], Al[0][3], aw_lo + ko);
            ldsm_x4(Al[1][0], Al[1][1], Al[1][2], Al[1][3], aw_lo + 16 * 528 + ko);
            const uint32_t bk = b_base + (uint32_t)(kstep * 16 * 272);
#pragma unroll
            for (int nb = 0; nb < 4; nb++) {
                uint32_t bh0, bh1, bl0, bl1;
                ldsm_x2t(bh0, bh1, bk + (uint32_t)(nb * 16));
                ldsm_x2t(bl0, bl1, bk + 8704 + (uint32_t)(nb * 16));
#pragma unroll
                for (int mb = 0; mb < 2; mb++) {
                    mma16816(acc[mb][nb], Ah[mb], bh0, bh1);
                    mma16816(acc[mb][nb], Ah[mb], bl0, bl1);
                    mma16816(acc[mb][nb], Al[mb], bh0, bh1);
                }
            }
        }
        __syncthreads();
#pragma unroll
        for (int j = 0; j < 16; j++) xp[j] = xn[j];
    }

    __nv_bfloat16* Dh = (__nv_bfloat16*)(sm1 + K1_DT);
    __nv_bfloat16* Dl = Dh + 9216;
#pragma unroll
    for (int mb = 0; mb < 2; mb++) {
#pragma unroll
        for (int nb = 0; nb < 4; nb++) {
            int m = warpm * 32 + mb * 16 + (lan >> 2);
            int p = warpn * 32 + nb * 8 + 2 * (lan & 3);
#pragma unroll
            for (int j = 0; j < 4; j++) {
                int mch = m + (j >> 1) * 8;
                int pp  = p + (j & 1);
                float v = acc[mb][nb][j] * scs[mch] + bis[mch];
                float sv = v / (1.f + __expf(-v));
                __nv_bfloat16 hi = __float2bfloat16(sv);
                Dh[pp * 72 + mch] = hi;
                Dl[pp * 72 + mch] = __float2bfloat16(sv - __bfloat162float(hi));
            }
        }
    }
    __syncthreads();

    for (int i = tid; i < 2048; i += 256) {
        int split = i >> 10, r = (i >> 3) & 127, ch8 = i & 7;
        uint4 v = *(const uint4*)(sm1 + K1_DT + split * 18432 + r * 144 + ch8 * 16);
        uint4* dst = (uint4*)(split ? g_midT_lo : g_midT_hi);
        dst[(size_t)(b * 6400 + px0 + r) * 8 + ch8] = v;
    }
}

// ---------------------------------------------------------------------------
// K2 v3: 3x3 conv via mma.sync bf16 split-3, cp.async double-buffered weights,
// ONE sync per tap (wait_group 0 -> sync -> restage -> compute) + x4 B loads.
// ---------------------------------------------------------------------------
#define SM_ACT_HI 0
#define SM_ACT_LO 25920
#define SM_WB0    51840       // 29952B each ([split 14976][104][144B])
#define SM_WB1    81792
// guard: 111744..113472 (1728B) absorbs nb6 overreach of WB1
#define SM_SCS    113472
#define SM_BIS    113872
#define SM_TOTAL  114272
#define WSPLIT    14976
#define DT_STRIDE 122

__global__ __launch_bounds__(256, 2)
void k2_enc(const float* __restrict__ g2, const float* __restrict__ b2,
            const float* __restrict__ m2, const float* __restrict__ v2)
{
    extern __shared__ __align__(16) char sm[];
    const int b  = blockIdx.z;
    const int h0 = blockIdx.y * 16;
    const int w0 = blockIdx.x * 8;
    const int tid = threadIdx.x;
    const int wid = tid >> 5;
    const int lan = tid & 31;
    const uint32_t smb = smem_u32(sm);

    if (tid < 100) {
        float is = g2[tid] * rsqrtf(v2[tid] + EPS);
        ((float*)(sm + SM_SCS))[tid] = is;
        ((float*)(sm + SM_BIS))[tid] = b2[tid] - m2[tid] * is;
    }

    // stage 18x10 activation tile (hi+lo)
    for (int k = tid; k < 2880; k += 256) {
        int bufi = (k >= 1440);
        int r = bufi ? k - 1440 : k;
        int row = r >> 3, ch = r & 7;
        int y = row / 10, x = row - y * 10;
        int gh = h0 + y - 1, gw = w0 + x - 1;
        uint4 v = make_uint4(0, 0, 0, 0);
        if (gh >= 0 && gh < HH && gw >= 0 && gw < WW) {
            const uint4* src = (const uint4*)(bufi ? g_midT_lo : g_midT_hi);
            v = src[(size_t)(b * 6400 + gh * WW + gw) * 8 + ch];
        }
        *(uint4*)(sm + (bufi ? SM_ACT_LO : SM_ACT_HI) + row * 144 + (ch << 4)) = v;
    }

#define K2_WSTAGE(tapx, bufoff) do {                                          \
        const uint4* gsrc = (const uint4*)g_weP + (tapx) * 1872;              \
        for (int k = tid; k < 1872; k += 256)                                 \
            cp_async16(smb + (bufoff) + (uint32_t)(k << 4), gsrc + k, 16);    \
        asm volatile("cp.async.commit_group;" ::: "memory");                  \
    } while (0)

    K2_WSTAGE(0, SM_WB0);

    const int warpm = wid & 3;
    const int warpn = wid >> 2;

    float acc[2][7][4];
#pragma unroll
    for (int mb = 0; mb < 2; mb++)
#pragma unroll
        for (int nb = 0; nb < 7; nb++)
#pragma unroll
            for (int j = 0; j < 4; j++) acc[mb][nb][j] = 0.f;

    const int pA0 = warpm * 32 + (lan & 15);
    const int pyA0 = pA0 >> 3, pxA0 = pA0 & 7;
    const uint32_t a_half = (uint32_t)((lan >> 4) << 4);
    // x4 B addressing: lanes 0-7/8-15 -> rows c..c+7 half0/1; 16-23/24-31 -> c+8..c+15
    const uint32_t row4 = (uint32_t)((lan & 7) + ((lan >> 4) << 3));
    const uint32_t half4 = (uint32_t)(((lan >> 3) & 1) << 4);
    const uint32_t wb4_off = ((uint32_t)warpn * 56 + row4) * 144 + half4;
    // x2 tail (nb=6) addressing
    const int cB = warpn * 56 + (lan & 7);
    const uint32_t b_half = (uint32_t)(((lan >> 3) & 1) << 4);
    const uint32_t wb_off = (uint32_t)cB * 144 + b_half;

    for (int tap = 0; tap < 9; tap++) {
        const int dy = tap / 3, dx = tap - dy * 3;
        asm volatile("cp.async.wait_group 0;" ::: "memory");   // own stage(tap) done
        __syncthreads();                                       // all visible; prev ldsm done
        if (tap + 1 < 9) {
            if ((tap + 1) & 1) K2_WSTAGE(tap + 1, SM_WB1);
            else               K2_WSTAGE(tap + 1, SM_WB0);
        }

        const uint32_t wbuf = smb + ((tap & 1) ? SM_WB1 : SM_WB0);
        const uint32_t wb4_hi = wbuf + wb4_off;
        const uint32_t wb4_lo = wb4_hi + WSPLIT;
        const uint32_t wb_hi6 = wbuf + wb_off + 6 * 1152;
        const uint32_t wb_lo6 = wb_hi6 + WSPLIT;

        uint32_t arow0 = (uint32_t)(((pyA0 + dy) * 10 + pxA0 + dx) * 144) + a_half;
        uint32_t arow1 = (uint32_t)(((((pA0 + 16) >> 3) + dy) * 10 + ((pA0 + 16) & 7) + dx) * 144) + a_half;

#pragma unroll
        for (int ks = 0; ks < 4; ks++) {
            const uint32_t ko = (uint32_t)(ks << 5);
            uint32_t Ah[2][4], Al[2][4];
            ldsm_x4(Ah[0][0], Ah[0][1], Ah[0][2], Ah[0][3], smb + SM_ACT_HI + arow0 + ko);
            ldsm_x4(Ah[1][0], Ah[1][1], Ah[1][2], Ah[1][3], smb + SM_ACT_HI + arow1 + ko);
            ldsm_x4(Al[0][0], Al[0][1], Al[0][2], Al[0][3], smb + SM_ACT_LO + arow0 + ko);
            ldsm_x4(Al[1][0], Al[1][1], Al[1][2], Al[1][3], smb + SM_ACT_LO + arow1 + ko);
#pragma unroll
            for (int pr = 0; pr < 3; pr++) {
                uint32_t bh[4], bl[4];
                ldsm_x4(bh[0], bh[1], bh[2], bh[3], wb4_hi + (uint32_t)(pr * 2304) + ko);
                ldsm_x4(bl[0], bl[1], bl[2], bl[3], wb4_lo + (uint32_t)(pr * 2304) + ko);
#pragma unroll
                for (int hfl = 0; hfl < 2; hfl++) {
                    const int nb = pr * 2 + hfl;
#pragma unroll
                    for (int mb = 0; mb < 2; mb++) {
                        mma16816(acc[mb][nb], Ah[mb], bh[2 * hfl], bh[2 * hfl + 1]);
                        mma16816(acc[mb][nb], Ah[mb], bl[2 * hfl], bl[2 * hfl + 1]);
                        mma16816(acc[mb][nb], Al[mb], bh[2 * hfl], bh[2 * hfl + 1]);
                    }
                }
            }
            {   // tail nb = 6
                uint32_t bh0, bh1, bl0, bl1;
                ldsm_x2(bh0, bh1, wb_hi6 + ko);
                ldsm_x2(bl0, bl1, wb_lo6 + ko);
#pragma unroll
                for (int mb = 0; mb < 2; mb++) {
                    mma16816(acc[mb][6], Ah[mb], bh0, bh1);
                    mma16816(acc[mb][6], Ah[mb], bl0, bl1);
                    mma16816(acc[mb][6], Al[mb], bh0, bh1);
                }
            }
        }
    }
    __syncthreads();

    float* Dt = (float*)sm;
#pragma unroll
    for (int mb = 0; mb < 2; mb++) {
        int r = warpm * 32 + mb * 16 + (lan >> 2);
#pragma unroll
        for (int nb = 0; nb < 7; nb++) {
            int c = warpn * 56 + nb * 8 + 2 * (lan & 3);
            *(float2*)&Dt[r * DT_STRIDE + c] = make_float2(acc[mb][nb][0], acc[mb][nb][1]);
            *(float2*)&Dt[(r + 8) * DT_STRIDE + c] = make_float2(acc[mb][nb][2], acc[mb][nb][3]);
        }
    }
    __syncthreads();

    const float* scs = (const float*)(sm + SM_SCS);
    const float* bis = (const float*)(sm + SM_BIS);
    for (int it = tid; it < 512; it += 256) {
        int p = it >> 2, q = it & 3;
        float v[25];
        float mx = -1e30f;
#pragma unroll
        for (int k = 0; k < 25; k++) {
            int m = (k << 2) + q;
            float x = Dt[p * DT_STRIDE + m] * scs[m] + bis[m];
            v[k] = x;
            mx = fmaxf(mx, x);
        }
        float s = 0.f;
#pragma unroll
        for (int k = 0; k < 25; k++) {
            float e = __expf(v[k] - mx);
            v[k] = e;
            s += e;
        }
        float inv = 1.f / s;
        int y = 2 * (h0 + (p >> 3)) + (q >> 1);
        int x = 2 * (w0 + (p & 7)) + (q & 1);
#pragma unroll
        for (int k = 0; k < 25; k++)
            g_wm[(((size_t)(b * K2T + k)) * HO + y) * WO + x] = v[k] * inv;
    }
}

// ---------------------------------------------------------------------------
// K3 v5: thread = (pixel, ch-group-of-8), all 4 subpixels per thread.
// ONE sync per cg: wait_group 0 -> sync -> restage(cg+1) -> compute(cg).
// ---------------------------------------------------------------------------
#define XST 36
#define K3_WS   0
#define K3_XS0  25600
#define K3_XS1  46336
#define K3_SMEM 67072

__global__ __launch_bounds__(256, 3) void k3_carafe(float* __restrict__ out)
{
    extern __shared__ __align__(16) char sm3[];
    float* Ws4 = (float*)(sm3 + K3_WS);

    const int b = blockIdx.y;
    const int h0 = (blockIdx.x / 10) * 8;
    const int w0 = (blockIdx.x % 10) * 8;
    const int tid = threadIdx.x;

    for (int i = tid; i < 3200; i += 256) {
        int kk = i >> 7, r = i & 127, si = r >> 6, p = r & 63;
        int hh = p >> 3, ww = p & 7;
        int y = 2 * (h0 + hh) + si, x = 2 * (w0 + ww);
        float2 v = *(const float2*)&g_wm[(((size_t)(b * K2T + kk)) * HO + y) * WO + x];
        Ws4[(kk * 64 + p) * 4 + si * 2 + 0] = v.x;
        Ws4[(kk * 64 + p) * 4 + si * 2 + 1] = v.y;
    }

    const float* Xb = g_xT + (size_t)b * 6400 * 256;

#define K3_STAGE(cgx, bufoff) do {                                               \
        for (int i = tid; i < 1152; i += 256) {                                  \
            int pos = i >> 3, c16 = i & 7;                                       \
            int dy = pos / 12, dx = pos - dy * 12;                               \
            int gh = h0 + dy - 2, gw = w0 + dx - 2;                              \
            bool ok = (gh >= 0 && gh < HH && gw >= 0 && gw < WW);                \
            const float* src = Xb + (size_t)(ok ? (gh * WW + gw) : 0) * 256      \
                               + (cgx) * 32 + c16 * 4;                           \
            cp_async16(smem_u32(sm3 + (bufoff)) + (uint32_t)((pos * XST + c16 * 4) * 4), \
                       src, ok ? 16u : 0u);                                      \
        }                                                                        \
        asm volatile("cp.async.commit_group;" ::: "memory");                     \
    } while (0)

    K3_STAGE(0, K3_XS0);

    const int px = tid >> 2, cg4 = tid & 3;
    const int h = px >> 3, w = px & 7;
    const uint32_t xoff = (uint32_t)(((h * 12 + w) * XST + cg4 * 8) * 4);
    const uint32_t wbase = smem_u32(sm3) + (uint32_t)(px * 16);
    const int y0 = 2 * (h0 + h), x0 = 2 * (w0 + w);

    for (int cg = 0; cg < 8; cg++) {
        asm volatile("cp.async.wait_group 0;" ::: "memory");   // own stage(cg) done
        __syncthreads();                                       // all visible; prev reads done
        if (cg + 1 < 8) {
            if ((cg + 1) & 1) K3_STAGE(cg + 1, K3_XS1);
            else              K3_STAGE(cg + 1, K3_XS0);
        }

        const uint32_t xb = smem_u32(sm3) + (uint32_t)((cg & 1) ? K3_XS1 : K3_XS0) + xoff;
        uint64_t acc[4][4];
#pragma unroll
        for (int s = 0; s < 4; s++)
#pragma unroll
            for (int k = 0; k < 4; k++) acc[s][k] = 0ull;

#pragma unroll
        for (int t = 0; t < 25; t++) {
            const int ki = t / 5, kj = t - ki * 5;
            const uint32_t off = (uint32_t)((ki * 12 + kj) * XST * 4);
            float4 wv;
            asm volatile("ld.shared.v4.f32 {%0,%1,%2,%3}, [%4];"
                         : "=f"(wv.x), "=f"(wv.y), "=f"(wv.z), "=f"(wv.w)
                         : "r"(wbase + (uint32_t)(t * 1024)));
            uint64_t w20 = bcast2(wv.x), w21 = bcast2(wv.y);
            uint64_t w22 = bcast2(wv.z), w23 = bcast2(wv.w);
            uint64_t xq0, xq1, xq2, xq3;
            lds_v2u64(xq0, xq1, xb + off);
            lds_v2u64(xq2, xq3, xb + off + 16);
            fma2(acc[0][0], xq0, w20); fma2(acc[0][1], xq1, w20);
            fma2(acc[0][2], xq2, w20); fma2(acc[0][3], xq3, w20);
            fma2(acc[1][0], xq0, w21); fma2(acc[1][1], xq1, w21);
            fma2(acc[1][2], xq2, w21); fma2(acc[1][3], xq3, w21);
            fma2(acc[2][0], xq0, w22); fma2(acc[2][1], xq1, w22);
            fma2(acc[2][2], xq2, w22); fma2(acc[2][3], xq3, w22);
            fma2(acc[3][0], xq0, w23); fma2(acc[3][1], xq1, w23);
            fma2(acc[3][2], xq2, w23); fma2(acc[3][3], xq3, w23);
        }

        float* ob = out + (((size_t)(b * CIN + cg * 32 + cg4 * 8)) * HO + y0) * WO + x0;
#pragma unroll
        for (int k = 0; k < 4; k++) {
            float s0a, s0b, s1a, s1b, s2a, s2b, s3a, s3b;
            unpack2(s0a, s0b, acc[0][k]);
            unpack2(s1a, s1b, acc[1][k]);
            unpack2(s2a, s2b, acc[2][k]);
            unpack2(s3a, s3b, acc[3][k]);
            float* p0 = ob + (size_t)(2 * k) * (HO * WO);
            float* p1 = p0 + HO * WO;
            *(float2*)p0        = make_float2(s0a, s1a);
            *(float2*)(p0 + WO) = make_float2(s2a, s3a);
            *(float2*)p1        = make_float2(s0b, s1b);
            *(float2*)(p1 + WO) = make_float2(s2b, s3b);
        }
    }
}

// ---------------------------------------------------------------------------
extern "C" void kernel_launch(void* const* d_in, const int* in_sizes, int n_in,
                              void* d_out, int out_size)
{
    const float* X  = (const float*)d_in[0];
    const float* Wc = (const float*)d_in[1];
    const float* g1 = (const float*)d_in[2];
    const float* b1 = (const float*)d_in[3];
    const float* m1 = (const float*)d_in[4];
    const float* v1 = (const float*)d_in[5];
    const float* We = (const float*)d_in[6];
    const float* g2 = (const float*)d_in[7];
    const float* b2 = (const float*)d_in[8];
    const float* m2 = (const float*)d_in[9];
    const float* v2 = (const float*)d_in[10];
    float* out = (float*)d_out;

    cudaFuncSetAttribute(k1_comp, cudaFuncAttributeMaxDynamicSharedMemorySize, K1_SMEM);
    cudaFuncSetAttribute(k2_enc, cudaFuncAttributeMaxDynamicSharedMemorySize, SM_TOTAL);
    cudaFuncSetAttribute(k3_carafe, cudaFuncAttributeMaxDynamicSharedMemorySize, K3_SMEM);

    k0_wprep<<<527, 256>>>(We);
    k0x_transpose<<<dim3(200, 8, BATCH), 256>>>(X);
    k1_comp<<<dim3(50, BATCH), 256, K1_SMEM>>>(X, Wc, g1, b1, m1, v1);
    k2_enc<<<dim3(10, 5, BATCH), 256, SM_TOTAL>>>(g2, b2, m2, v2);
    k3_carafe<<<dim3(100, BATCH), 256, K3_SMEM>>>(out);
}

// round 10
// speedup vs baseline: 1.5610x; 1.0231x over previous
#include <cuda_runtime.h>
#include <cuda_bf16.h>
#include <cstdint>

#define BATCH 16
#define CIN   256
#define HH    80
#define WW    80
#define CMID  64
#define K2T   25
#define HO    160
#define WO    160
#define EPS   1e-5f

// ---------------------------------------------------------------------------
// Device scratch (allocation-free)
// ---------------------------------------------------------------------------
__device__ __align__(16) __nv_bfloat16 g_midT_hi[(size_t)BATCH * 6400 * 64]; // [b][pix][c]
__device__ __align__(16) __nv_bfloat16 g_midT_lo[(size_t)BATCH * 6400 * 64];
// per-tap weights, n-major: [tap][split][c(104)][ic(72)] bf16
__device__ __align__(16) __nv_bfloat16 g_weP[9 * 2 * 104 * 72];
__device__ __align__(16) float g_wm[(size_t)BATCH * K2T * HO * WO];
__device__ __align__(16) float g_xT[(size_t)BATCH * 6400 * 256];   // X pixel-major, 105MB

__device__ __forceinline__ uint32_t smem_u32(const void* p) {
    uint32_t a;
    asm("{ .reg .u64 t; cvta.to.shared.u64 t, %1; cvt.u32.u64 %0, t; }" : "=r"(a) : "l"(p));
    return a;
}
__device__ __forceinline__ void ldsm_x4(uint32_t& r0, uint32_t& r1, uint32_t& r2, uint32_t& r3,
                                        uint32_t addr) {
    asm volatile("ldmatrix.sync.aligned.m8n8.x4.shared.b16 {%0,%1,%2,%3}, [%4];"
                 : "=r"(r0), "=r"(r1), "=r"(r2), "=r"(r3) : "r"(addr));
}
__device__ __forceinline__ void ldsm_x2(uint32_t& r0, uint32_t& r1, uint32_t addr) {
    asm volatile("ldmatrix.sync.aligned.m8n8.x2.shared.b16 {%0,%1}, [%2];"
                 : "=r"(r0), "=r"(r1) : "r"(addr));
}
__device__ __forceinline__ void ldsm_x2t(uint32_t& r0, uint32_t& r1, uint32_t addr) {
    asm volatile("ldmatrix.sync.aligned.m8n8.x2.trans.shared.b16 {%0,%1}, [%2];"
                 : "=r"(r0), "=r"(r1) : "r"(addr));
}
__device__ __forceinline__ void mma16816(float* d, const uint32_t* a, uint32_t b0, uint32_t b1) {
    asm volatile(
        "mma.sync.aligned.m16n8k16.row.col.f32.bf16.bf16.f32 "
        "{%0,%1,%2,%3}, {%4,%5,%6,%7}, {%8,%9}, {%0,%1,%2,%3};"
        : "+f"(d[0]), "+f"(d[1]), "+f"(d[2]), "+f"(d[3])
        : "r"(a[0]), "r"(a[1]), "r"(a[2]), "r"(a[3]), "r"(b0), "r"(b1));
}
// Packed fp32 helpers (Blackwell f32x2 pipe)
__device__ __forceinline__ void fma2(uint64_t& d, uint64_t a, uint64_t b) {
    asm("fma.rn.f32x2 %0, %1, %2, %0;" : "+l"(d) : "l"(a), "l"(b));
}
__device__ __forceinline__ uint64_t bcast2(float x) {
    uint64_t r;
    asm("mov.b64 %0, {%1, %1};" : "=l"(r) : "f"(x));
    return r;
}
__device__ __forceinline__ void unpack2(float& lo, float& hi, uint64_t v) {
    asm("mov.b64 {%0, %1}, %2;" : "=f"(lo), "=f"(hi) : "l"(v));
}
__device__ __forceinline__ void lds_v2u64(uint64_t& a, uint64_t& b, uint32_t addr) {
    asm volatile("ld.shared.v2.u64 {%0, %1}, [%2];" : "=l"(a), "=l"(b) : "r"(addr));
}
__device__ __forceinline__ void cp_async16(uint32_t saddr, const void* gptr, uint32_t sz) {
    asm volatile("cp.async.cg.shared.global [%0], [%1], 16, %2;"
                 :: "r"(saddr), "l"(gptr), "r"(sz) : "memory");
}

// ---------------------------------------------------------------------------
// K0: conv2 weights -> [tap][split][c pad 104][ic pad 72] bf16 split
// ---------------------------------------------------------------------------
__global__ __launch_bounds__(256) void k0_wprep(const float* __restrict__ We) {
    int i = blockIdx.x * 256 + threadIdx.x;
    if (i >= 9 * 2 * 104 * 72) return;
    int tap = i / 14976, r = i % 14976;
    int s = r / 7488; r %= 7488;
    int c = r / 72, ic = r % 72;
    float v = (c < 100 && ic < 64) ? We[c * 576 + ic * 9 + tap] : 0.f;
    __nv_bfloat16 hi = __float2bfloat16(v);
    g_weP[i] = s ? __float2bfloat16(v - __bfloat162float(hi)) : hi;
}

// ---------------------------------------------------------------------------
// K1 v3: 1x1 conv (256->64) via mma.sync bf16 split-3 + BN + SiLU.
// ALSO writes the X transpose g_xT[b][px][c] (fp32) from its staged chunks,
// eliminating the standalone k0x transpose kernel. Bytes identical to k0x.
// ---------------------------------------------------------------------------
#define K1_SW    0            // weights hi [64][528B] = 33792; lo at +33792
#define K1_SXS   67584        // X chunk bf16 [split][32k][272B] = 8704*2
#define K1_SBN   84992        // scs 256B + bis 256B
#define K1_XT32  85504        // fp32 transpose buffer [128px][36f] = 18432B
#define K1_SMEM  103936
#define K1_DT    0            // epilogue [split][128px][144B], reuses weights

__global__ __launch_bounds__(256, 2) void k1_comp(
    const float* __restrict__ X, const float* __restrict__ Wc,
    const float* __restrict__ g1, const float* __restrict__ b1,
    const float* __restrict__ m1, const float* __restrict__ v1)
{
    extern __shared__ __align__(16) char sm1[];
    const int b   = blockIdx.y;
    const int px0 = blockIdx.x * 128;
    const int tid = threadIdx.x;
    const int wid = tid >> 5, lan = tid & 31;
    const uint32_t smb = smem_u32(sm1);

    __nv_bfloat16* Wh = (__nv_bfloat16*)(sm1 + K1_SW);
    __nv_bfloat16* Wl = Wh + 16896;
    for (int i = tid; i < 16384; i += 256) {
        int m = i >> 8, k = i & 255;
        float v = Wc[i];
        __nv_bfloat16 hi = __float2bfloat16(v);
        Wh[m * 264 + k] = hi;
        Wl[m * 264 + k] = __float2bfloat16(v - __bfloat162float(hi));
    }
    float* scs = (float*)(sm1 + K1_SBN);
    float* bis = scs + 64;
    if (tid < 64) {
        float is = g1[tid] * rsqrtf(v1[tid] + EPS);
        scs[tid] = is;
        bis[tid] = b1[tid] - m1[tid] * is;
    }

    const float* Xb = X + (size_t)b * 256 * 6400 + px0;
    __nv_bfloat16* Xh = (__nv_bfloat16*)(sm1 + K1_SXS);
    __nv_bfloat16* Xl = Xh + 4352;
    float* XT = (float*)(sm1 + K1_XT32);

    float xp[16];
#pragma unroll
    for (int j = 0; j < 16; j++) {
        int e = j * 256 + tid;
        xp[j] = Xb[(size_t)(e >> 7) * 6400 + (e & 127)];
    }

    const int warpm = wid & 1;
    const int warpn = wid >> 1;

    float acc[2][4][4];
#pragma unroll
    for (int mb = 0; mb < 2; mb++)
#pragma unroll
        for (int nb = 0; nb < 4; nb++)
#pragma unroll
            for (int j = 0; j < 4; j++) acc[mb][nb][j] = 0.f;

    const uint32_t a_row = (uint32_t)(warpm * 32 + (lan & 15));
    const uint32_t a_half = (uint32_t)((lan >> 4) << 4);
    const uint32_t aw_hi = smb + K1_SW + a_row * 528 + a_half;
    const uint32_t aw_lo = aw_hi + 33792;
    const uint32_t b_base = smb + K1_SXS + (uint32_t)((lan & 15) * 272 + warpn * 64);

#pragma unroll 1
    for (int cg = 0; cg < 8; cg++) {
        // store staged chunk: bf16 split (MMA operand) + fp32 (transpose out)
#pragma unroll
        for (int j = 0; j < 16; j++) {
            int e = j * 256 + tid;
            int kr = e >> 7, px = e & 127;
            float v = xp[j];
            __nv_bfloat16 hi = __float2bfloat16(v);
            Xh[kr * 136 + px] = hi;
            Xl[kr * 136 + px] = __float2bfloat16(v - __bfloat162float(hi));
            XT[px * 36 + kr] = v;
        }
        __syncthreads();

        // write-out g_xT for this chunk (coalesced float4)
        {
            float* dst = g_xT + ((size_t)(b * 6400 + px0)) * 256 + cg * 32;
            for (int i = tid; i < 1024; i += 256) {
                int px = i >> 3, c4 = i & 7;
                float4 v = *(float4*)&XT[px * 36 + c4 * 4];
                *(float4*)&dst[(size_t)px * 256 + c4 * 4] = v;
            }
        }

        float xn[16];
        if (cg < 7) {
#pragma unroll
            for (int j = 0; j < 16; j++) {
                int e = j * 256 + tid;
                xn[j] = Xb[(size_t)((cg + 1) * 32 + (e >> 7)) * 6400 + (e & 127)];
            }
        }

        const uint32_t kco = (uint32_t)(cg * 64);
#pragma unroll
        for (int kstep = 0; kstep < 2; kstep++) {
            const uint32_t ko = kco + (uint32_t)(kstep * 32);
            uint32_t Ah[2][4], Al[2][4];
            ldsm_x4(Ah[0][0], Ah[0][1], Ah[0][2], Ah[0][3], aw_hi + ko);
            ldsm_x4(Ah[1][0], Ah[1][1], Ah[1][2], Ah[1][3], aw_hi + 16 * 528 + ko);
            ldsm_x4(Al[0][0], Al[0][1], Al[0][2], Al[0][3], aw_lo + ko);
            ldsm_x4(Al[1][0], Al[1][1], Al[1][2], Al[1][3], aw_lo + 16 * 528 + ko);
            const uint32_t bk = b_base + (uint32_t)(kstep * 16 * 272);
#pragma unroll
            for (int nb = 0; nb < 4; nb++) {
                uint32_t bh0, bh1, bl0, bl1;
                ldsm_x2t(bh0, bh1, bk + (uint32_t)(nb * 16));
                ldsm_x2t(bl0, bl1, bk + 8704 + (uint32_t)(nb * 16));
#pragma unroll
                for (int mb = 0; mb < 2; mb++) {
                    mma16816(acc[mb][nb], Ah[mb], bh0, bh1);
                    mma16816(acc[mb][nb], Ah[mb], bl0, bl1);
                    mma16816(acc[mb][nb], Al[mb], bh0, bh1);
                }
            }
        }
        __syncthreads();
#pragma unroll
        for (int j = 0; j < 16; j++) xp[j] = xn[j];
    }

    __nv_bfloat16* Dh = (__nv_bfloat16*)(sm1 + K1_DT);
    __nv_bfloat16* Dl = Dh + 9216;
#pragma unroll
    for (int mb = 0; mb < 2; mb++) {
#pragma unroll
        for (int nb = 0; nb < 4; nb++) {
            int m = warpm * 32 + mb * 16 + (lan >> 2);
            int p = warpn * 32 + nb * 8 + 2 * (lan & 3);
#pragma unroll
            for (int j = 0; j < 4; j++) {
                int mch = m + (j >> 1) * 8;
                int pp  = p + (j & 1);
                float v = acc[mb][nb][j] * scs[mch] + bis[mch];
                float sv = v / (1.f + __expf(-v));
                __nv_bfloat16 hi = __float2bfloat16(sv);
                Dh[pp * 72 + mch] = hi;
                Dl[pp * 72 + mch] = __float2bfloat16(sv - __bfloat162float(hi));
            }
        }
    }
    __syncthreads();

    for (int i = tid; i < 2048; i += 256) {
        int split = i >> 10, r = (i >> 3) & 127, ch8 = i & 7;
        uint4 v = *(const uint4*)(sm1 + K1_DT + split * 18432 + r * 144 + ch8 * 16);
        uint4* dst = (uint4*)(split ? g_midT_lo : g_midT_hi);
        dst[(size_t)(b * 6400 + px0 + r) * 8 + ch8] = v;
    }
}

// ---------------------------------------------------------------------------
// K2 v3: 3x3 conv via mma.sync bf16 split-3, cp.async double-buffered weights,
// ONE sync per tap (wait_group 0 -> sync -> restage -> compute) + x4 B loads.
// ---------------------------------------------------------------------------
#define SM_ACT_HI 0
#define SM_ACT_LO 25920
#define SM_WB0    51840       // 29952B each ([split 14976][104][144B])
#define SM_WB1    81792
// guard: 111744..113472 (1728B) absorbs nb6 overreach of WB1
#define SM_SCS    113472
#define SM_BIS    113872
#define SM_TOTAL  114272
#define WSPLIT    14976
#define DT_STRIDE 122

__global__ __launch_bounds__(256, 2)
void k2_enc(const float* __restrict__ g2, const float* __restrict__ b2,
            const float* __restrict__ m2, const float* __restrict__ v2)
{
    extern __shared__ __align__(16) char sm[];
    const int b  = blockIdx.z;
    const int h0 = blockIdx.y * 16;
    const int w0 = blockIdx.x * 8;
    const int tid = threadIdx.x;
    const int wid = tid >> 5;
    const int lan = tid & 31;
    const uint32_t smb = smem_u32(sm);

    if (tid < 100) {
        float is = g2[tid] * rsqrtf(v2[tid] + EPS);
        ((float*)(sm + SM_SCS))[tid] = is;
        ((float*)(sm + SM_BIS))[tid] = b2[tid] - m2[tid] * is;
    }

    // stage 18x10 activation tile (hi+lo)
    for (int k = tid; k < 2880; k += 256) {
        int bufi = (k >= 1440);
        int r = bufi ? k - 1440 : k;
        int row = r >> 3, ch = r & 7;
        int y = row / 10, x = row - y * 10;
        int gh = h0 + y - 1, gw = w0 + x - 1;
        uint4 v = make_uint4(0, 0, 0, 0);
        if (gh >= 0 && gh < HH && gw >= 0 && gw < WW) {
            const uint4* src = (const uint4*)(bufi ? g_midT_lo : g_midT_hi);
            v = src[(size_t)(b * 6400 + gh * WW + gw) * 8 + ch];
        }
        *(uint4*)(sm + (bufi ? SM_ACT_LO : SM_ACT_HI) + row * 144 + (ch << 4)) = v;
    }

#define K2_WSTAGE(tapx, bufoff) do {                                          \
        const uint4* gsrc = (const uint4*)g_weP + (tapx) * 1872;              \
        for (int k = tid; k < 1872; k += 256)                                 \
            cp_async16(smb + (bufoff) + (uint32_t)(k << 4), gsrc + k, 16);    \
        asm volatile("cp.async.commit_group;" ::: "memory");                  \
    } while (0)

    K2_WSTAGE(0, SM_WB0);

    const int warpm = wid & 3;
    const int warpn = wid >> 2;

    float acc[2][7][4];
#pragma unroll
    for (int mb = 0; mb < 2; mb++)
#pragma unroll
        for (int nb = 0; nb < 7; nb++)
#pragma unroll
            for (int j = 0; j < 4; j++) acc[mb][nb][j] = 0.f;

    const int pA0 = warpm * 32 + (lan & 15);
    const int pyA0 = pA0 >> 3, pxA0 = pA0 & 7;
    const uint32_t a_half = (uint32_t)((lan >> 4) << 4);
    // x4 B addressing: lanes 0-7/8-15 -> rows c..c+7 half0/1; 16-23/24-31 -> c+8..c+15
    const uint32_t row4 = (uint32_t)((lan & 7) + ((lan >> 4) << 3));
    const uint32_t half4 = (uint32_t)(((lan >> 3) & 1) << 4);
    const uint32_t wb4_off = ((uint32_t)warpn * 56 + row4) * 144 + half4;
    // x2 tail (nb=6) addressing
    const int cB = warpn * 56 + (lan & 7);
    const uint32_t b_half = (uint32_t)(((lan >> 3) & 1) << 4);
    const uint32_t wb_off = (uint32_t)cB * 144 + b_half;

    for (int tap = 0; tap < 9; tap++) {
        const int dy = tap / 3, dx = tap - dy * 3;
        asm volatile("cp.async.wait_group 0;" ::: "memory");   // own stage(tap) done
        __syncthreads();                                       // all visible; prev ldsm done
        if (tap + 1 < 9) {
            if ((tap + 1) & 1) K2_WSTAGE(tap + 1, SM_WB1);
            else               K2_WSTAGE(tap + 1, SM_WB0);
        }

        const uint32_t wbuf = smb + ((tap & 1) ? SM_WB1 : SM_WB0);
        const uint32_t wb4_hi = wbuf + wb4_off;
        const uint32_t wb4_lo = wb4_hi + WSPLIT;
        const uint32_t wb_hi6 = wbuf + wb_off + 6 * 1152;
        const uint32_t wb_lo6 = wb_hi6 + WSPLIT;

        uint32_t arow0 = (uint32_t)(((pyA0 + dy) * 10 + pxA0 + dx) * 144) + a_half;
        uint32_t arow1 = (uint32_t)(((((pA0 + 16) >> 3) + dy) * 10 + ((pA0 + 16) & 7) + dx) * 144) + a_half;

#pragma unroll
        for (int ks = 0; ks < 4; ks++) {
            const uint32_t ko = (uint32_t)(ks << 5);
            uint32_t Ah[2][4], Al[2][4];
            ldsm_x4(Ah[0][0], Ah[0][1], Ah[0][2], Ah[0][3], smb + SM_ACT_HI + arow0 + ko);
            ldsm_x4(Ah[1][0], Ah[1][1], Ah[1][2], Ah[1][3], smb + SM_ACT_HI + arow1 + ko);
            ldsm_x4(Al[0][0], Al[0][1], Al[0][2], Al[0][3], smb + SM_ACT_LO + arow0 + ko);
            ldsm_x4(Al[1][0], Al[1][1], Al[1][2], Al[1][3], smb + SM_ACT_LO + arow1 + ko);
#pragma unroll
            for (int pr = 0; pr < 3; pr++) {
                uint32_t bh[4], bl[4];
                ldsm_x4(bh[0], bh[1], bh[2], bh[3], wb4_hi + (uint32_t)(pr * 2304) + ko);
                ldsm_x4(bl[0], bl[1], bl[2], bl[3], wb4_lo + (uint32_t)(pr * 2304) + ko);
#pragma unroll
                for (int hfl = 0; hfl < 2; hfl++) {
                    const int nb = pr * 2 + hfl;
#pragma unroll
                    for (int mb = 0; mb < 2; mb++) {
                        mma16816(acc[mb][nb], Ah[mb], bh[2 * hfl], bh[2 * hfl + 1]);
                        mma16816(acc[mb][nb], Ah[mb], bl[2 * hfl], bl[2 * hfl + 1]);
                        mma16816(acc[mb][nb], Al[mb], bh[2 * hfl], bh[2 * hfl + 1]);
                    }
                }
            }
            {   // tail nb = 6
                uint32_t bh0, bh1, bl0, bl1;
                ldsm_x2(bh0, bh1, wb_hi6 + ko);
                ldsm_x2(bl0, bl1, wb_lo6 + ko);
#pragma unroll
                for (int mb = 0; mb < 2; mb++) {
                    mma16816(acc[mb][6], Ah[mb], bh0, bh1);
                    mma16816(acc[mb][6], Ah[mb], bl0, bl1);
                    mma16816(acc[mb][6], Al[mb], bh0, bh1);
                }
            }
        }
    }
    __syncthreads();

    float* Dt = (float*)sm;
#pragma unroll
    for (int mb = 0; mb < 2; mb++) {
        int r = warpm * 32 + mb * 16 + (lan >> 2);
#pragma unroll
        for (int nb = 0; nb < 7; nb++) {
            int c = warpn * 56 + nb * 8 + 2 * (lan & 3);
            *(float2*)&Dt[r * DT_STRIDE + c] = make_float2(acc[mb][nb][0], acc[mb][nb][1]);
            *(float2*)&Dt[(r + 8) * DT_STRIDE + c] = make_float2(acc[mb][nb][2], acc[mb][nb][3]);
        }
    }
    __syncthreads();

    const float* scs = (const float*)(sm + SM_SCS);
    const float* bis = (const float*)(sm + SM_BIS);
    for (int it = tid; it < 512; it += 256) {
        int p = it >> 2, q = it & 3;
        float v[25];
        float mx = -1e30f;
#pragma unroll
        for (int k = 0; k < 25; k++) {
            int m = (k << 2) + q;
            float x = Dt[p * DT_STRIDE + m] * scs[m] + bis[m];
            v[k] = x;
            mx = fmaxf(mx, x);
        }
        float s = 0.f;
#pragma unroll
        for (int k = 0; k < 25; k++) {
            float e = __expf(v[k] - mx);
            v[k] = e;
            s += e;
        }
        float inv = 1.f / s;
        int y = 2 * (h0 + (p >> 3)) + (q >> 1);
        int x = 2 * (w0 + (p & 7)) + (q & 1);
#pragma unroll
        for (int k = 0; k < 25; k++)
            g_wm[(((size_t)(b * K2T + k)) * HO + y) * WO + x] = v[k] * inv;
    }
}

// ---------------------------------------------------------------------------
// K3 v5: thread = (pixel, ch-group-of-8), all 4 subpixels per thread.
// ONE sync per cg: wait_group 0 -> sync -> restage(cg+1) -> compute(cg).
// ---------------------------------------------------------------------------
#define XST 36
#define K3_WS   0
#define K3_XS0  25600
#define K3_XS1  46336
#define K3_SMEM 67072

__global__ __launch_bounds__(256, 3) void k3_carafe(float* __restrict__ out)
{
    extern __shared__ __align__(16) char sm3[];
    float* Ws4 = (float*)(sm3 + K3_WS);

    const int b = blockIdx.y;
    const int h0 = (blockIdx.x / 10) * 8;
    const int w0 = (blockIdx.x % 10) * 8;
    const int tid = threadIdx.x;

    for (int i = tid; i < 3200; i += 256) {
        int kk = i >> 7, r = i & 127, si = r >> 6, p = r & 63;
        int hh = p >> 3, ww = p & 7;
        int y = 2 * (h0 + hh) + si, x = 2 * (w0 + ww);
        float2 v = *(const float2*)&g_wm[(((size_t)(b * K2T + kk)) * HO + y) * WO + x];
        Ws4[(kk * 64 + p) * 4 + si * 2 + 0] = v.x;
        Ws4[(kk * 64 + p) * 4 + si * 2 + 1] = v.y;
    }

    const float* Xb = g_xT + (size_t)b * 6400 * 256;

#define K3_STAGE(cgx, bufoff) do {                                               \
        for (int i = tid; i < 1152; i += 256) {                                  \
            int pos = i >> 3, c16 = i & 7;                                       \
            int dy = pos / 12, dx = pos - dy * 12;                               \
            int gh = h0 + dy - 2, gw = w0 + dx - 2;                              \
            bool ok = (gh >= 0 && gh < HH && gw >= 0 && gw < WW);                \
            const float* src = Xb + (size_t)(ok ? (gh * WW + gw) : 0) * 256      \
                               + (cgx) * 32 + c16 * 4;                           \
            cp_async16(smem_u32(sm3 + (bufoff)) + (uint32_t)((pos * XST + c16 * 4) * 4), \
                       src, ok ? 16u : 0u);                                      \
        }                                                                        \
        asm volatile("cp.async.commit_group;" ::: "memory");                     \
    } while (0)

    K3_STAGE(0, K3_XS0);

    const int px = tid >> 2, cg4 = tid & 3;
    const int h = px >> 3, w = px & 7;
    const uint32_t xoff = (uint32_t)(((h * 12 + w) * XST + cg4 * 8) * 4);
    const uint32_t wbase = smem_u32(sm3) + (uint32_t)(px * 16);
    const int y0 = 2 * (h0 + h), x0 = 2 * (w0 + w);

    for (int cg = 0; cg < 8; cg++) {
        asm volatile("cp.async.wait_group 0;" ::: "memory");   // own stage(cg) done
        __syncthreads();                                       // all visible; prev reads done
        if (cg + 1 < 8) {
            if ((cg + 1) & 1) K3_STAGE(cg + 1, K3_XS1);
            else              K3_STAGE(cg + 1, K3_XS0);
        }

        const uint32_t xb = smem_u32(sm3) + (uint32_t)((cg & 1) ? K3_XS1 : K3_XS0) + xoff;
        uint64_t acc[4][4];
#pragma unroll
        for (int s = 0; s < 4; s++)
#pragma unroll
            for (int k = 0; k < 4; k++) acc[s][k] = 0ull;

#pragma unroll
        for (int t = 0; t < 25; t++) {
            const int ki = t / 5, kj = t - ki * 5;
            const uint32_t off = (uint32_t)((ki * 12 + kj) * XST * 4);
            float4 wv;
            asm volatile("ld.shared.v4.f32 {%0,%1,%2,%3}, [%4];"
                         : "=f"(wv.x), "=f"(wv.y), "=f"(wv.z), "=f"(wv.w)
                         : "r"(wbase + (uint32_t)(t * 1024)));
            uint64_t w20 = bcast2(wv.x), w21 = bcast2(wv.y);
            uint64_t w22 = bcast2(wv.z), w23 = bcast2(wv.w);
            uint64_t xq0, xq1, xq2, xq3;
            lds_v2u64(xq0, xq1, xb + off);
            lds_v2u64(xq2, xq3, xb + off + 16);
            fma2(acc[0][0], xq0, w20); fma2(acc[0][1], xq1, w20);
            fma2(acc[0][2], xq2, w20); fma2(acc[0][3], xq3, w20);
            fma2(acc[1][0], xq0, w21); fma2(acc[1][1], xq1, w21);
            fma2(acc[1][2], xq2, w21); fma2(acc[1][3], xq3, w21);
            fma2(acc[2][0], xq0, w22); fma2(acc[2][1], xq1, w22);
            fma2(acc[2][2], xq2, w22); fma2(acc[2][3], xq3, w22);
            fma2(acc[3][0], xq0, w23); fma2(acc[3][1], xq1, w23);
            fma2(acc[3][2], xq2, w23); fma2(acc[3][3], xq3, w23);
        }

        float* ob = out + (((size_t)(b * CIN + cg * 32 + cg4 * 8)) * HO + y0) * WO + x0;
#pragma unroll
        for (int k = 0; k < 4; k++) {
            float s0a, s0b, s1a, s1b, s2a, s2b, s3a, s3b;
            unpack2(s0a, s0b, acc[0][k]);
            unpack2(s1a, s1b, acc[1][k]);
            unpack2(s2a, s2b, acc[2][k]);
            unpack2(s3a, s3b, acc[3][k]);
            float* p0 = ob + (size_t)(2 * k) * (HO * WO);
            float* p1 = p0 + HO * WO;
            *(float2*)p0        = make_float2(s0a, s1a);
            *(float2*)(p0 + WO) = make_float2(s2a, s3a);
            *(float2*)p1        = make_float2(s0b, s1b);
            *(float2*)(p1 + WO) = make_float2(s2b, s3b);
        }
    }
}

// ---------------------------------------------------------------------------
extern "C" void kernel_launch(void* const* d_in, const int* in_sizes, int n_in,
                              void* d_out, int out_size)
{
    const float* X  = (const float*)d_in[0];
    const float* Wc = (const float*)d_in[1];
    const float* g1 = (const float*)d_in[2];
    const float* b1 = (const float*)d_in[3];
    const float* m1 = (const float*)d_in[4];
    const float* v1 = (const float*)d_in[5];
    const float* We = (const float*)d_in[6];
    const float* g2 = (const float*)d_in[7];
    const float* b2 = (const float*)d_in[8];
    const float* m2 = (const float*)d_in[9];
    const float* v2 = (const float*)d_in[10];
    float* out = (float*)d_out;

    cudaFuncSetAttribute(k1_comp, cudaFuncAttributeMaxDynamicSharedMemorySize, K1_SMEM);
    cudaFuncSetAttribute(k2_enc, cudaFuncAttributeMaxDynamicSharedMemorySize, SM_TOTAL);
    cudaFuncSetAttribute(k3_carafe, cudaFuncAttributeMaxDynamicSharedMemorySize, K3_SMEM);

    k0_wprep<<<527, 256>>>(We);
    k1_comp<<<dim3(50, BATCH), 256, K1_SMEM>>>(X, Wc, g1, b1, m1, v1);
    k2_enc<<<dim3(10, 5, BATCH), 256, SM_TOTAL>>>(g2, b2, m2, v2);
    k3_carafe<<<dim3(100, BATCH), 256, K3_SMEM>>>(out);
}